// round 8
// baseline (speedup 1.0000x reference)
#include <cuda_runtime.h>
#include <cuda_bf16.h>
#include <cuda_fp16.h>
#include <cuda_fp8.h>
#include <math.h>
#include <stdint.h>

#define D        512
#define KK       32
#define PP       528
#define MROWS    128
#define KCH      64
#define NCHUNK   9
#define NTHREADS 512
#define NMAX     102400

#define H_STRIDE 592
#define ZQ_STRIDE 272
#define V_STRIDE 80
#define U_STRIDE 80
#define VCHUNK_BYTES (256 * V_STRIDE)   // 20480
#define VCHUNK_U4    1280

// ---------- kernel A smem ----------
#define SMA_GID   0
#define SMA_KERN  512
#define SMA_PBUF  1024
#define SMA_ZMU   3072
#define SMA_COORD 5120
#define SMA_U     22016
#define SMA_ZQ    62976
#define SMA_TOTAL 97792

// ---------- kernel B smem ----------
#define SMB_GID   0
#define SMB_KERN  512
#define SMB_CHG   1024
#define SMB_LUT   3072
#define SMB_COORD 4224
#define SMB_V     21120
#define SMB_H     82560
#define SMB_TOTAL 158336

__device__ float g_change[D];
__device__ float g_zmu[D];
__device__ float g_xcU[KK];
__device__ float g_dU[KK];
__device__ __align__(16) unsigned short g_iup[544];
__device__ __align__(16) unsigned char g_Ubf[512 * U_STRIDE];
__device__ __align__(16) unsigned char g_V8[18 * VCHUNK_BYTES];
__device__ float g_coords[(size_t)NMAX * KK];
__device__ float g_kern[NMAX];

__device__ __forceinline__ uint32_t smem_u32(const void* p) {
    uint32_t a;
    asm("{ .reg .u64 t; cvta.to.shared.u64 t, %1; cvt.u32.u64 %0, t; }" : "=r"(a) : "l"(p));
    return a;
}
__device__ __forceinline__ void ldsm4(uint32_t* r, uint32_t a) {
    asm volatile("ldmatrix.sync.aligned.m8n8.x4.shared.b16 {%0,%1,%2,%3}, [%4];"
                 : "=r"(r[0]), "=r"(r[1]), "=r"(r[2]), "=r"(r[3]) : "r"(a));
}
__device__ __forceinline__ void ldsm4t(uint32_t* r, uint32_t a) {
    asm volatile("ldmatrix.sync.aligned.m8n8.x4.trans.shared.b16 {%0,%1,%2,%3}, [%4];"
                 : "=r"(r[0]), "=r"(r[1]), "=r"(r[2]), "=r"(r[3]) : "r"(a));
}
__device__ __forceinline__ void mma16816(float* c, const uint32_t* a, const uint32_t* b) {
    asm volatile("mma.sync.aligned.m16n8k16.row.col.f32.bf16.bf16.f32 "
                 "{%0,%1,%2,%3}, {%4,%5,%6,%7}, {%8,%9}, {%0,%1,%2,%3};"
                 : "+f"(c[0]), "+f"(c[1]), "+f"(c[2]), "+f"(c[3])
                 : "r"(a[0]), "r"(a[1]), "r"(a[2]), "r"(a[3]), "r"(b[0]), "r"(b[1]));
}
// fp8 x fp8 -> fp16 accumulate (the experiment: 2x rate hypothesis)
__device__ __forceinline__ void mma8h(uint32_t* c, const uint32_t* a, uint32_t b0, uint32_t b1) {
    asm volatile("mma.sync.aligned.m16n8k32.row.col.f16.e4m3.e4m3.f16 "
                 "{%0,%1}, {%2,%3,%4,%5}, {%6,%7}, {%0,%1};"
                 : "+r"(c[0]), "+r"(c[1])
                 : "r"(a[0]), "r"(a[1]), "r"(a[2]), "r"(a[3]), "r"(b0), "r"(b1));
}
__device__ __forceinline__ uint32_t pack4_e4m3(float f0, float f1, float f2, float f3) {
    uint32_t r;
    asm("{\n\t.reg .b16 lo, hi;\n\t"
        "cvt.rn.satfinite.e4m3x2.f32 lo, %2, %1;\n\t"
        "cvt.rn.satfinite.e4m3x2.f32 hi, %4, %3;\n\t"
        "mov.b32 %0, {lo, hi};\n\t}"
        : "=r"(r) : "f"(f0), "f"(f1), "f"(f2), "f"(f3));
    return r;
}
__device__ __forceinline__ void cp16(uint32_t saddr, const void* g) {
    asm volatile("cp.async.cg.shared.global [%0], [%1], 16;" :: "r"(saddr), "l"(g));
}
__device__ __forceinline__ void cp_commit() {
    asm volatile("cp.async.commit_group;" ::: "memory");
}
template <int N>
__device__ __forceinline__ void cp_wait() {
    asm volatile("cp.async.wait_group %0;" :: "n"(N) : "memory");
}

// ===================== prep =====================
__global__ void prep_kernel(const float* __restrict__ U,
                            const float* __restrict__ V,
                            const float* __restrict__ zmu,
                            const float* __restrict__ xc) {
    int b = blockIdx.x, t = threadIdx.x;
    if (b < 288) {
        int g = b * 256 + t;
        int chunk = g >> 12;
        int rem = g & 4095;
        int n = rem >> 4;
        int k4 = (rem & 15) << 2;
        int np = chunk / NCHUNK, c = chunk - np * NCHUNK;
        int gk = c * KCH + k4;
        int gn = np * 256 + n;
        float4 v = make_float4(0.f, 0.f, 0.f, 0.f);
        if (gk < PP) v = *(const float4*)(V + (size_t)gn * PP + gk);
        uint32_t w = pack4_e4m3(v.x * 256.f, v.y * 256.f, v.z * 256.f, v.w * 256.f);
        *(uint32_t*)(g_V8 + (size_t)chunk * VCHUNK_BYTES + n * V_STRIDE + k4) = w;
        return;
    }
    if (b < 368) {
        int e = (b - 288) * 256 + t;
        int k = e / 40, n = e - k * 40;
        float v = (n < KK) ? U[k * KK + n] : 0.f;
        *(__nv_bfloat16*)(g_Ubf + k * U_STRIDE + n * 2) = __float2bfloat16(v);
        return;
    }
    __shared__ float pa[256], pb[256], sdiff[KK];
    {
        int j = t & 31, seg = t >> 5;
        float a = 0.f, bb = 0.f;
        for (int i = 0; i < 64; ++i) {
            int d = seg * 64 + i;
            float u = U[d * KK + j];
            a = fmaf(zmu[d], u, a);
            bb = fmaf(xc[d], u, bb);
        }
        pa[t] = a; pb[t] = bb;
    }
    __syncthreads();
    if (t < KK) {
        float sa = 0.f, sb = 0.f;
        for (int s = 0; s < 8; ++s) { sa += pa[s * 32 + t]; sb += pb[s * 32 + t]; }
        g_xcU[t] = sb;
        g_dU[t]  = sb - sa;
        sdiff[t] = sb - sa;
    }
    __syncthreads();
    for (int d = t; d < D; d += 256) {
        float s = 0.f;
        for (int j = 0; j < KK; ++j) s = fmaf(sdiff[j], U[d * KK + j], s);
        g_change[d] = xc[d] - zmu[d] - s;
        g_zmu[d] = zmu[d];
    }
    if (t == 0) {
        int p = 0;
        for (int i = 0; i < KK; ++i)
            for (int j = i; j < KK; ++j) {
                g_iup[p] = (unsigned short)(i | (j << 8));
                ++p;
            }
        for (; p < 544; ++p) g_iup[p] = 0;
    }
}

// ===================== kernel A: coords + kern =====================
__global__ __launch_bounds__(NTHREADS, 2)
void kernelA(const float* __restrict__ Z_all,
             const int*   __restrict__ choice,
             int Nc) {
    extern __shared__ __align__(16) char sm[];
    const uint32_t smb = smem_u32(sm);
    int*   gid    = (int*)(sm + SMA_GID);
    float* pbuf   = (float*)(sm + SMA_PBUF);
    float* zmus   = (float*)(sm + SMA_ZMU);
    float* coords = (float*)(sm + SMA_COORD);

    const int tid = threadIdx.x;
    const int wid = tid >> 5;
    const int lid = tid & 31;
    const int n0  = blockIdx.x * MROWS;

    if (tid < MROWS) {
        int n = n0 + tid;
        gid[tid] = (n < Nc) ? choice[n] : -1;
    }
    zmus[tid] = g_zmu[tid];
    {
        const uint4* s = (const uint4*)g_Ubf;
        uint4* d = (uint4*)(sm + SMA_U);
        #pragma unroll
        for (int i = 0; i < 5; ++i) d[tid + i * 512] = s[tid + i * 512];
    }
    __syncthreads();

    const int nh = (wid >> 3) * 16;
    float zu[2][4];
    #pragma unroll
    for (int i = 0; i < 2; ++i)
        #pragma unroll
        for (int j = 0; j < 4; ++j) zu[i][j] = 0.f;

    const int r  = tid >> 2, q4 = tid & 3;
    const int g  = gid[r];
    const float4* zrowg = (const float4*)(Z_all + (size_t)(g < 0 ? 0 : g) * D) + q4 * 8;
    char* zrow = sm + SMA_ZQ + r * ZQ_STRIDE + q4 * 64;

    const uint32_t zbase = smb + SMA_ZQ + (uint32_t)((wid & 7) * 16 + (lid & 15)) * ZQ_STRIDE;
    const uint32_t kh    = (uint32_t)(lid >> 4) * 16;
    const uint32_t ubase = smb + SMA_U +
                           (uint32_t)((lid & 7) + 8 * ((lid >> 3) & 1)) * U_STRIDE +
                           (uint32_t)(nh + 8 * (lid >> 4)) * 2;

    float accn = 0.f;
    for (int q = 0; q < 4; ++q) {
        #pragma unroll 4
        for (int i = 0; i < 8; ++i) {
            float4 z = make_float4(0.f, 0.f, 0.f, 0.f);
            if (g >= 0) z = zrowg[q * 32 + i];
            int d0 = q * 128 + q4 * 32 + i * 4;
            float a0 = z.x - zmus[d0], a1 = z.y - zmus[d0 + 1];
            float a2 = z.z - zmus[d0 + 2], a3 = z.w - zmus[d0 + 3];
            accn = fmaf(a0, a0, fmaf(a1, a1, fmaf(a2, a2, fmaf(a3, a3, accn))));
            __nv_bfloat162 p0 = __floats2bfloat162_rn(z.x, z.y);
            __nv_bfloat162 p1 = __floats2bfloat162_rn(z.z, z.w);
            *(uint32_t*)(zrow + i * 8)     = *(uint32_t*)&p0;
            *(uint32_t*)(zrow + i * 8 + 4) = *(uint32_t*)&p1;
        }
        if (q == 3) pbuf[tid] = accn;
        __syncthreads();
        #pragma unroll 4
        for (int ks = 0; ks < 8; ++ks) {
            uint32_t a[4], b[4];
            ldsm4(a, zbase + (uint32_t)(ks * 32) + kh);
            ldsm4t(b, ubase + (uint32_t)((q * 128 + ks * 16) * U_STRIDE));
            mma16816(zu[0], a, b);
            mma16816(zu[1], a, b + 2);
        }
        __syncthreads();
    }

    {
        int r0 = (wid & 7) * 16 + (lid >> 2);
        int c0 = (lid & 3) * 2;
        #pragma unroll
        for (int nt = 0; nt < 2; ++nt) {
            int c = nh + nt * 8 + c0;
            coords[r0 * 33 + c]           = zu[nt][0] - g_xcU[c];
            coords[r0 * 33 + c + 1]       = zu[nt][1] - g_xcU[c + 1];
            coords[(r0 + 8) * 33 + c]     = zu[nt][2] - g_xcU[c];
            coords[(r0 + 8) * 33 + c + 1] = zu[nt][3] - g_xcU[c + 1];
        }
    }
    __syncthreads();

    #pragma unroll
    for (int e = tid; e < MROWS * KK; e += NTHREADS) {
        int rr = e >> 5, j = e & 31;
        g_coords[((size_t)n0 + rr) * KK + j] = coords[rr * 33 + j];
    }

    if (tid < MROWS) {
        const float* cr = coords + tid * 33;
        float un = 0.f;
        #pragma unroll
        for (int j = 0; j < KK; ++j) {
            float v = cr[j] + g_dU[j];
            un = fmaf(v, v, un);
        }
        float zn = pbuf[4 * tid] + pbuf[4 * tid + 1] + pbuf[4 * tid + 2] + pbuf[4 * tid + 3];
        float C = zn - un;
        float E = __expf(-0.01f * un);
        float x_m2 = C * 0.999f;
        float x_m1 = C;
        bool done = false;
        for (int it = 0; it < 100; ++it) {
            if (done) break;
            float t1 = 1.f - E * __expf(-0.01f * x_m1);
            float f1 = t1 * t1 * x_m1 - C;
            float t2 = 1.f - E * __expf(-0.01f * x_m2);
            float f2 = t2 * t2 * x_m2 - C;
            float fd = f1 - f2;
            if (fabsf(fd) < 1e-6f) fd = (fd >= 0.f) ? 1e-6f : -1e-6f;
            float x = x_m1 - f1 * (x_m1 - x_m2) / fd;
            float step = fabsf(x - x_m1);
            x_m2 = x_m1;
            x_m1 = x;
            done = (step < 1e-6f);
        }
        g_kern[n0 + tid] = __expf(-0.01f * (un + x_m1));
    }
}

// ===================== kernel B: H GEMM (fp16 accum) + epilogue ==========
__global__ __launch_bounds__(NTHREADS, 1)
void kernelB(const float* __restrict__ Z_all,
             const int*   __restrict__ choice,
             float*       __restrict__ out,
             int Nc) {
    extern __shared__ __align__(16) char sm[];
    const uint32_t smb = smem_u32(sm);
    int*   gid    = (int*)(sm + SMB_GID);
    float* kern   = (float*)(sm + SMB_KERN);
    float* chg    = (float*)(sm + SMB_CHG);
    float* coords = (float*)(sm + SMB_COORD);

    const int tid = threadIdx.x;
    const int wid = tid >> 5;
    const int lid = tid & 31;
    const int n0  = blockIdx.x * MROWS;

    {
        const char* src = (const char*)g_V8;
        #pragma unroll
        for (int i = 0; i < 3; ++i) {
            int idx = tid + i * 512;
            if (idx < VCHUNK_U4) cp16(smb + SMB_V + idx * 16, src + (size_t)idx * 16);
        }
        cp_commit();
    }

    if (tid < MROWS) {
        int n = n0 + tid;
        gid[tid]  = (n < Nc) ? choice[n] : -1;
        kern[tid] = g_kern[n0 + tid];
    }
    chg[tid] = g_change[tid];
    if (tid < 136) ((uint2*)(sm + SMB_LUT))[tid] = ((const uint2*)g_iup)[tid];
    #pragma unroll
    for (int e = tid; e < MROWS * KK; e += NTHREADS) {
        int rr = e >> 5, j = e & 31;
        coords[rr * 33 + j] = g_coords[((size_t)n0 + rr) * KK + j];
    }
    __syncthreads();

    {
        int m = tid >> 2, seg = tid & 3;
        const float* cr = coords + m * 33;
        char* hrow = sm + SMB_H + m * H_STRIDE;
        const unsigned short* lut = (const unsigned short*)(sm + SMB_LUT);
        int p0 = seg * 144, p1 = p0 + 144;
        for (int p = p0; p < p1; p += 4) {
            uint32_t w = 0;
            if (p < PP) {
                uint2 lu = *(const uint2*)(lut + p);
                int a0 = lu.x & 255, b0 = (lu.x >> 8) & 255;
                int a1 = (lu.x >> 16) & 255, b1 = (lu.x >> 24) & 255;
                int a2 = lu.y & 255, b2 = (lu.y >> 8) & 255;
                int a3 = (lu.y >> 16) & 255, b3 = (lu.y >> 24) & 255;
                w = pack4_e4m3(cr[a0] * cr[b0], cr[a1] * cr[b1],
                               cr[a2] * cr[b2], cr[a3] * cr[b3]);
            }
            *(uint32_t*)(hrow + p) = w;
        }
    }

    const int mg = (wid >> 2) * 32;
    const int ng = (wid & 3) * 64;
    const uint32_t hlane = smb + SMB_H + (uint32_t)(mg + (lid & 15)) * H_STRIDE +
                           (uint32_t)((lid >> 4) * 16);
    const uint32_t vlane = (uint32_t)(ng + (lid & 7) + 8 * ((lid >> 4) & 1)) * V_STRIDE +
                           (uint32_t)(((lid >> 3) & 1) * 16);
    const float INV256 = 0.00390625f;

    float accf[2][8][4];
    uint32_t acc16[2][8][2];
    #pragma unroll
    for (int i = 0; i < 2; ++i)
        #pragma unroll
        for (int j = 0; j < 8; ++j) {
            #pragma unroll
            for (int q = 0; q < 4; ++q) accf[i][j][q] = 0.f;
            acc16[i][j][0] = 0u; acc16[i][j][1] = 0u;
        }

    for (int t = 0; t < 18; ++t) {
        if (t + 1 < 18) {
            const char* src = (const char*)(g_V8 + (size_t)(t + 1) * VCHUNK_BYTES);
            uint32_t dstb = smb + SMB_V + (uint32_t)(((t + 1) % 3) * VCHUNK_BYTES);
            #pragma unroll
            for (int i = 0; i < 3; ++i) {
                int idx = tid + i * 512;
                if (idx < VCHUNK_U4) cp16(dstb + idx * 16, src + (size_t)idx * 16);
            }
            cp_commit();
            cp_wait<1>();
        } else {
            cp_wait<0>();
        }
        __syncthreads();

        const int c = (t >= NCHUNK) ? t - NCHUNK : t;
        const uint32_t vb = smb + SMB_V + (uint32_t)((t % 3) * VCHUNK_BYTES) + vlane;
        #pragma unroll
        for (int ks = 0; ks < 2; ++ks) {
            uint32_t a[2][4];
            uint32_t koff = (uint32_t)(c * KCH + ks * 32);
            ldsm4(a[0], hlane + koff);
            ldsm4(a[1], hlane + (uint32_t)(16 * H_STRIDE) + koff);
            #pragma unroll
            for (int q = 0; q < 4; ++q) {
                uint32_t bfrag[4];
                ldsm4(bfrag, vb + (uint32_t)(q * 16) * V_STRIDE + (uint32_t)(ks * 32));
                mma8h(acc16[0][2 * q],     a[0], bfrag[0], bfrag[1]);
                mma8h(acc16[0][2 * q + 1], a[0], bfrag[2], bfrag[3]);
                mma8h(acc16[1][2 * q],     a[1], bfrag[0], bfrag[1]);
                mma8h(acc16[1][2 * q + 1], a[1], bfrag[2], bfrag[3]);
            }
        }

        // flush fp16 partials -> fp32 every 3 chunks (covers t==8 and t==17)
        if (t % 3 == 2) {
            #pragma unroll
            for (int mt = 0; mt < 2; ++mt)
                #pragma unroll
                for (int nt = 0; nt < 8; ++nt) {
                    float2 lo = __half22float2(*(__half2*)&acc16[mt][nt][0]);
                    float2 hi = __half22float2(*(__half2*)&acc16[mt][nt][1]);
                    accf[mt][nt][0] += lo.x;
                    accf[mt][nt][1] += lo.y;
                    accf[mt][nt][2] += hi.x;
                    accf[mt][nt][3] += hi.y;
                    acc16[mt][nt][0] = 0u;
                    acc16[mt][nt][1] = 0u;
                }
        }

        if (t == NCHUNK - 1 || t == 17) {
            const int np = (t == NCHUNK - 1) ? 0 : 1;
            int r0 = mg + (lid >> 2);
            int c0 = np * 256 + ng + (lid & 3) * 2;
            #pragma unroll
            for (int mt = 0; mt < 2; ++mt) {
                int rA = r0 + mt * 16, rB = rA + 8;
                int gA = gid[rA], gB = gid[rB];
                float kA = kern[rA], kB = kern[rB];
                #pragma unroll
                for (int nt = 0; nt < 8; ++nt) {
                    int col = c0 + nt * 8;
                    float ca = chg[col], cb = chg[col + 1];
                    if (gA >= 0) {
                        float2 z = *(const float2*)(Z_all + (size_t)gA * D + col);
                        float2 o;
                        o.x = z.x + kA * (ca + accf[mt][nt][0] * INV256);
                        o.y = z.y + kA * (cb + accf[mt][nt][1] * INV256);
                        *(float2*)(out + (size_t)gA * D + col) = o;
                    }
                    if (gB >= 0) {
                        float2 z = *(const float2*)(Z_all + (size_t)gB * D + col);
                        float2 o;
                        o.x = z.x + kB * (ca + accf[mt][nt][2] * INV256);
                        o.y = z.y + kB * (cb + accf[mt][nt][3] * INV256);
                        *(float2*)(out + (size_t)gB * D + col) = o;
                    }
                    if (np == 0) {
                        accf[mt][nt][0] = 0.f; accf[mt][nt][1] = 0.f;
                        accf[mt][nt][2] = 0.f; accf[mt][nt][3] = 0.f;
                    }
                }
            }
        }
    }
}

// ===================== launch =====================
extern "C" void kernel_launch(void* const* d_in, const int* in_sizes, int n_in,
                              void* d_out, int out_size) {
    const float* Z_all  = (const float*)d_in[0];
    const float* U      = (const float*)d_in[1];
    const float* V      = (const float*)d_in[2];
    const float* zmu    = (const float*)d_in[3];
    const float* xc     = (const float*)d_in[4];
    const int*   choice = (const int*)  d_in[5];
    float*       out    = (float*)d_out;
    const int Nc = in_sizes[5];

    if ((size_t)Nc * D != (size_t)in_sizes[0]) {
        cudaMemcpyAsync(d_out, Z_all, (size_t)in_sizes[0] * sizeof(float),
                        cudaMemcpyDeviceToDevice, 0);
    }

    prep_kernel<<<369, 256>>>(U, V, zmu, xc);

    int nblocks = (Nc + MROWS - 1) / MROWS;
    cudaFuncSetAttribute(kernelA, cudaFuncAttributeMaxDynamicSharedMemorySize, SMA_TOTAL);
    cudaFuncSetAttribute(kernelB, cudaFuncAttributeMaxDynamicSharedMemorySize, SMB_TOTAL);
    kernelA<<<nblocks, NTHREADS, SMA_TOTAL>>>(Z_all, choice, Nc);
    kernelB<<<nblocks, NTHREADS, SMB_TOTAL>>>(Z_all, choice, out, Nc);
}

// round 9
// speedup vs baseline: 1.0131x; 1.0131x over previous
#include <cuda_runtime.h>
#include <cuda_bf16.h>
#include <cuda_fp8.h>
#include <math.h>
#include <stdint.h>

#define D        512
#define KK       32
#define PP       528
#define MROWS    128               // kernel A tile
#define MB       64                // kernel B tile
#define KCH      64
#define NCHUNK   9
#define NTHREADS 512
#define NMAX     102400

#define H_STRIDE 592
#define ZQ_STRIDE 272
#define V_STRIDE 80
#define U_STRIDE 80
#define VCHUNK_BYTES (256 * V_STRIDE)   // 20480
#define VCHUNK_U4    1280

// ---------- kernel A smem ----------
#define SMA_GID   0
#define SMA_KERN  512
#define SMA_PBUF  1024
#define SMA_ZMU   3072
#define SMA_COORD 5120
#define SMA_U     22016
#define SMA_ZQ    62976
#define SMA_TOTAL 97792

// ---------- kernel B smem (M=64, 2 CTAs/SM) ----------
#define SMB_GID   0                // 64 int
#define SMB_KERN  256              // 64 f
#define SMB_CHG   512              // 512 f = 2048
#define SMB_LUT   2560             // 1088
#define SMB_COORD 3664             // 64*33*4 = 8448
#define SMB_V     12160            // 3*20480 = 61440
#define SMB_H     73600            // 64*592 = 37888
#define SMB_TOTAL 111488           // x2 = 222976 <= 228KB

__device__ float g_change[D];
__device__ float g_zmu[D];
__device__ float g_xcU[KK];
__device__ float g_dU[KK];
__device__ __align__(16) unsigned short g_iup[544];
__device__ __align__(16) unsigned char g_Ubf[512 * U_STRIDE];
__device__ __align__(16) unsigned char g_V8[18 * VCHUNK_BYTES];
__device__ float g_coords[(size_t)NMAX * KK];
__device__ float g_kern[NMAX];

__device__ __forceinline__ uint32_t smem_u32(const void* p) {
    uint32_t a;
    asm("{ .reg .u64 t; cvta.to.shared.u64 t, %1; cvt.u32.u64 %0, t; }" : "=r"(a) : "l"(p));
    return a;
}
__device__ __forceinline__ void ldsm4(uint32_t* r, uint32_t a) {
    asm volatile("ldmatrix.sync.aligned.m8n8.x4.shared.b16 {%0,%1,%2,%3}, [%4];"
                 : "=r"(r[0]), "=r"(r[1]), "=r"(r[2]), "=r"(r[3]) : "r"(a));
}
__device__ __forceinline__ void ldsm4t(uint32_t* r, uint32_t a) {
    asm volatile("ldmatrix.sync.aligned.m8n8.x4.trans.shared.b16 {%0,%1,%2,%3}, [%4];"
                 : "=r"(r[0]), "=r"(r[1]), "=r"(r[2]), "=r"(r[3]) : "r"(a));
}
__device__ __forceinline__ void mma16816(float* c, const uint32_t* a, const uint32_t* b) {
    asm volatile("mma.sync.aligned.m16n8k16.row.col.f32.bf16.bf16.f32 "
                 "{%0,%1,%2,%3}, {%4,%5,%6,%7}, {%8,%9}, {%0,%1,%2,%3};"
                 : "+f"(c[0]), "+f"(c[1]), "+f"(c[2]), "+f"(c[3])
                 : "r"(a[0]), "r"(a[1]), "r"(a[2]), "r"(a[3]), "r"(b[0]), "r"(b[1]));
}
__device__ __forceinline__ void mma8(float* c, const uint32_t* a, uint32_t b0, uint32_t b1) {
    asm volatile("mma.sync.aligned.m16n8k32.row.col.f32.e4m3.e4m3.f32 "
                 "{%0,%1,%2,%3}, {%4,%5,%6,%7}, {%8,%9}, {%0,%1,%2,%3};"
                 : "+f"(c[0]), "+f"(c[1]), "+f"(c[2]), "+f"(c[3])
                 : "r"(a[0]), "r"(a[1]), "r"(a[2]), "r"(a[3]), "r"(b0), "r"(b1));
}
__device__ __forceinline__ uint32_t pack4_e4m3(float f0, float f1, float f2, float f3) {
    uint32_t r;
    asm("{\n\t.reg .b16 lo, hi;\n\t"
        "cvt.rn.satfinite.e4m3x2.f32 lo, %2, %1;\n\t"
        "cvt.rn.satfinite.e4m3x2.f32 hi, %4, %3;\n\t"
        "mov.b32 %0, {lo, hi};\n\t}"
        : "=r"(r) : "f"(f0), "f"(f1), "f"(f2), "f"(f3));
    return r;
}
__device__ __forceinline__ void cp16(uint32_t saddr, const void* g) {
    asm volatile("cp.async.cg.shared.global [%0], [%1], 16;" :: "r"(saddr), "l"(g));
}
__device__ __forceinline__ void cp_commit() {
    asm volatile("cp.async.commit_group;" ::: "memory");
}
template <int N>
__device__ __forceinline__ void cp_wait() {
    asm volatile("cp.async.wait_group %0;" :: "n"(N) : "memory");
}

// ===================== prep =====================
__global__ void prep_kernel(const float* __restrict__ U,
                            const float* __restrict__ V,
                            const float* __restrict__ zmu,
                            const float* __restrict__ xc) {
    int b = blockIdx.x, t = threadIdx.x;
    if (b < 288) {
        int g = b * 256 + t;
        int chunk = g >> 12;
        int rem = g & 4095;
        int n = rem >> 4;
        int k4 = (rem & 15) << 2;
        int np = chunk / NCHUNK, c = chunk - np * NCHUNK;
        int gk = c * KCH + k4;
        int gn = np * 256 + n;
        float4 v = make_float4(0.f, 0.f, 0.f, 0.f);
        if (gk < PP) v = *(const float4*)(V + (size_t)gn * PP + gk);
        uint32_t w = pack4_e4m3(v.x * 256.f, v.y * 256.f, v.z * 256.f, v.w * 256.f);
        *(uint32_t*)(g_V8 + (size_t)chunk * VCHUNK_BYTES + n * V_STRIDE + k4) = w;
        return;
    }
    if (b < 368) {
        int e = (b - 288) * 256 + t;
        int k = e / 40, n = e - k * 40;
        float v = (n < KK) ? U[k * KK + n] : 0.f;
        *(__nv_bfloat16*)(g_Ubf + k * U_STRIDE + n * 2) = __float2bfloat16(v);
        return;
    }
    __shared__ float pa[256], pb[256], sdiff[KK];
    {
        int j = t & 31, seg = t >> 5;
        float a = 0.f, bb = 0.f;
        for (int i = 0; i < 64; ++i) {
            int d = seg * 64 + i;
            float u = U[d * KK + j];
            a = fmaf(zmu[d], u, a);
            bb = fmaf(xc[d], u, bb);
        }
        pa[t] = a; pb[t] = bb;
    }
    __syncthreads();
    if (t < KK) {
        float sa = 0.f, sb = 0.f;
        for (int s = 0; s < 8; ++s) { sa += pa[s * 32 + t]; sb += pb[s * 32 + t]; }
        g_xcU[t] = sb;
        g_dU[t]  = sb - sa;
        sdiff[t] = sb - sa;
    }
    __syncthreads();
    for (int d = t; d < D; d += 256) {
        float s = 0.f;
        for (int j = 0; j < KK; ++j) s = fmaf(sdiff[j], U[d * KK + j], s);
        g_change[d] = xc[d] - zmu[d] - s;
        g_zmu[d] = zmu[d];
    }
    // triu LUT: parallel over p
    for (int p = t; p < 544; p += 256) {
        unsigned short v = 0;
        if (p < PP) {
            int i = 0, base = 0;
            while (base + (KK - i) <= p) { base += KK - i; ++i; }
            int j = i + (p - base);
            v = (unsigned short)(i | (j << 8));
        }
        g_iup[p] = v;
    }
}

// ===================== kernel A: coords + kern (M=128, occ 2) ==========
__global__ __launch_bounds__(NTHREADS, 2)
void kernelA(const float* __restrict__ Z_all,
             const int*   __restrict__ choice,
             int Nc) {
    extern __shared__ __align__(16) char sm[];
    const uint32_t smb = smem_u32(sm);
    int*   gid    = (int*)(sm + SMA_GID);
    float* pbuf   = (float*)(sm + SMA_PBUF);
    float* zmus   = (float*)(sm + SMA_ZMU);
    float* coords = (float*)(sm + SMA_COORD);

    const int tid = threadIdx.x;
    const int wid = tid >> 5;
    const int lid = tid & 31;
    const int n0  = blockIdx.x * MROWS;

    if (tid < MROWS) {
        int n = n0 + tid;
        gid[tid] = (n < Nc) ? choice[n] : -1;
    }
    zmus[tid] = g_zmu[tid];
    {
        const uint4* s = (const uint4*)g_Ubf;
        uint4* d = (uint4*)(sm + SMA_U);
        #pragma unroll
        for (int i = 0; i < 5; ++i) d[tid + i * 512] = s[tid + i * 512];
    }
    __syncthreads();

    const int nh = (wid >> 3) * 16;
    float zu[2][4];
    #pragma unroll
    for (int i = 0; i < 2; ++i)
        #pragma unroll
        for (int j = 0; j < 4; ++j) zu[i][j] = 0.f;

    const int r  = tid >> 2, q4 = tid & 3;
    const int g  = gid[r];
    const float4* zrowg = (const float4*)(Z_all + (size_t)(g < 0 ? 0 : g) * D) + q4 * 8;
    char* zrow = sm + SMA_ZQ + r * ZQ_STRIDE + q4 * 64;

    const uint32_t zbase = smb + SMA_ZQ + (uint32_t)((wid & 7) * 16 + (lid & 15)) * ZQ_STRIDE;
    const uint32_t kh    = (uint32_t)(lid >> 4) * 16;
    const uint32_t ubase = smb + SMA_U +
                           (uint32_t)((lid & 7) + 8 * ((lid >> 3) & 1)) * U_STRIDE +
                           (uint32_t)(nh + 8 * (lid >> 4)) * 2;

    float accn = 0.f;
    for (int q = 0; q < 4; ++q) {
        #pragma unroll 4
        for (int i = 0; i < 8; ++i) {
            float4 z = make_float4(0.f, 0.f, 0.f, 0.f);
            if (g >= 0) z = zrowg[q * 32 + i];
            int d0 = q * 128 + q4 * 32 + i * 4;
            float a0 = z.x - zmus[d0], a1 = z.y - zmus[d0 + 1];
            float a2 = z.z - zmus[d0 + 2], a3 = z.w - zmus[d0 + 3];
            accn = fmaf(a0, a0, fmaf(a1, a1, fmaf(a2, a2, fmaf(a3, a3, accn))));
            __nv_bfloat162 p0 = __floats2bfloat162_rn(z.x, z.y);
            __nv_bfloat162 p1 = __floats2bfloat162_rn(z.z, z.w);
            *(uint32_t*)(zrow + i * 8)     = *(uint32_t*)&p0;
            *(uint32_t*)(zrow + i * 8 + 4) = *(uint32_t*)&p1;
        }
        if (q == 3) pbuf[tid] = accn;
        __syncthreads();
        #pragma unroll 4
        for (int ks = 0; ks < 8; ++ks) {
            uint32_t a[4], b[4];
            ldsm4(a, zbase + (uint32_t)(ks * 32) + kh);
            ldsm4t(b, ubase + (uint32_t)((q * 128 + ks * 16) * U_STRIDE));
            mma16816(zu[0], a, b);
            mma16816(zu[1], a, b + 2);
        }
        __syncthreads();
    }

    {
        int r0 = (wid & 7) * 16 + (lid >> 2);
        int c0 = (lid & 3) * 2;
        #pragma unroll
        for (int nt = 0; nt < 2; ++nt) {
            int c = nh + nt * 8 + c0;
            coords[r0 * 33 + c]           = zu[nt][0] - g_xcU[c];
            coords[r0 * 33 + c + 1]       = zu[nt][1] - g_xcU[c + 1];
            coords[(r0 + 8) * 33 + c]     = zu[nt][2] - g_xcU[c];
            coords[(r0 + 8) * 33 + c + 1] = zu[nt][3] - g_xcU[c + 1];
        }
    }
    __syncthreads();

    #pragma unroll
    for (int e = tid; e < MROWS * KK; e += NTHREADS) {
        int rr = e >> 5, j = e & 31;
        g_coords[((size_t)n0 + rr) * KK + j] = coords[rr * 33 + j];
    }

    if (tid < MROWS) {
        const float* cr = coords + tid * 33;
        float un = 0.f;
        #pragma unroll
        for (int j = 0; j < KK; ++j) {
            float v = cr[j] + g_dU[j];
            un = fmaf(v, v, un);
        }
        float zn = pbuf[4 * tid] + pbuf[4 * tid + 1] + pbuf[4 * tid + 2] + pbuf[4 * tid + 3];
        float C = zn - un;
        float E = __expf(-0.01f * un);
        float x_m2 = C * 0.999f;
        float x_m1 = C;
        bool done = false;
        for (int it = 0; it < 100; ++it) {
            if (done) break;
            float t1 = 1.f - E * __expf(-0.01f * x_m1);
            float f1 = t1 * t1 * x_m1 - C;
            float t2 = 1.f - E * __expf(-0.01f * x_m2);
            float f2 = t2 * t2 * x_m2 - C;
            float fd = f1 - f2;
            if (fabsf(fd) < 1e-6f) fd = (fd >= 0.f) ? 1e-6f : -1e-6f;
            float x = x_m1 - f1 * (x_m1 - x_m2) / fd;
            float step = fabsf(x - x_m1);
            x_m2 = x_m1;
            x_m1 = x;
            done = (step < 1e-6f);
        }
        g_kern[n0 + tid] = __expf(-0.01f * (un + x_m1));
    }
}

// ===================== kernel B: M=64 GEMM + epilogue (occ 2) ==========
__global__ __launch_bounds__(NTHREADS, 2)
void kernelB(const float* __restrict__ Z_all,
             const int*   __restrict__ choice,
             float*       __restrict__ out,
             int Nc) {
    extern __shared__ __align__(16) char sm[];
    const uint32_t smb = smem_u32(sm);
    int*   gid    = (int*)(sm + SMB_GID);
    float* kern   = (float*)(sm + SMB_KERN);
    float* chg    = (float*)(sm + SMB_CHG);
    float* coords = (float*)(sm + SMB_COORD);

    const int tid = threadIdx.x;
    const int wid = tid >> 5;
    const int lid = tid & 31;
    const int n0  = blockIdx.x * MB;

    // V chunk 0 copy first (static addresses)
    {
        const char* src = (const char*)g_V8;
        #pragma unroll
        for (int i = 0; i < 3; ++i) {
            int idx = tid + i * 512;
            if (idx < VCHUNK_U4) cp16(smb + SMB_V + idx * 16, src + (size_t)idx * 16);
        }
        cp_commit();
    }

    if (tid < MB) {
        int n = n0 + tid;
        gid[tid]  = (n < Nc) ? choice[n] : -1;
        kern[tid] = (n < Nc) ? g_kern[n] : 0.f;
    }
    if (tid < D) chg[tid] = g_change[tid];
    if (tid < 136) ((uint2*)(sm + SMB_LUT))[tid] = ((const uint2*)g_iup)[tid];
    {   // coords tile: 64 rows x 32 f  (one uint4 per thread)
        int rr = tid >> 3, j4 = (tid & 7) * 4;
        float4 c4 = *(const float4*)(g_coords + ((size_t)n0 + rr) * KK + j4);
        coords[rr * 33 + j4]     = c4.x;
        coords[rr * 33 + j4 + 1] = c4.y;
        coords[rr * 33 + j4 + 2] = c4.z;
        coords[rr * 33 + j4 + 3] = c4.w;
    }
    __syncthreads();

    // ---- build H[64][576] fp8: lanes of a warp share a row (broadcast LDS) ----
    {
        const unsigned short* lut = (const unsigned short*)(sm + SMB_LUT);
        #pragma unroll
        for (int r = 0; r < 4; ++r) {
            int m = wid * 4 + r;
            const float* cr = coords + m * 33;
            char* hrow = sm + SMB_H + m * H_STRIDE;
            #pragma unroll
            for (int it = 0; it < 5; ++it) {
                int gp = lid + it * 32;
                if (gp < 144) {
                    int p = gp * 4;
                    uint32_t w = 0;
                    if (p < PP) {
                        uint2 lu = *(const uint2*)(lut + p);
                        int a0 = lu.x & 255, b0 = (lu.x >> 8) & 255;
                        int a1 = (lu.x >> 16) & 255, b1 = (lu.x >> 24) & 255;
                        int a2 = lu.y & 255, b2 = (lu.y >> 8) & 255;
                        int a3 = (lu.y >> 16) & 255, b3 = (lu.y >> 24) & 255;
                        w = pack4_e4m3(cr[a0] * cr[b0], cr[a1] * cr[b1],
                                       cr[a2] * cr[b2], cr[a3] * cr[b3]);
                    }
                    *(uint32_t*)(hrow + p) = w;
                }
            }
        }
    }

    // ---- main GEMM: warp tile 32 rows x 32 cols; 18 flat chunks ----
    const int mg = (wid >> 3) * 32;       // 0 / 32
    const int ng = (wid & 7) * 32;        // 0..224
    const uint32_t hlane = smb + SMB_H + (uint32_t)(mg + (lid & 15)) * H_STRIDE +
                           (uint32_t)((lid >> 4) * 16);
    const uint32_t vlane = (uint32_t)(ng + (lid & 7) + 8 * ((lid >> 4) & 1)) * V_STRIDE +
                           (uint32_t)(((lid >> 3) & 1) * 16);
    const float INV256 = 0.00390625f;

    float acc[2][4][4];
    #pragma unroll
    for (int i = 0; i < 2; ++i)
        #pragma unroll
        for (int j = 0; j < 4; ++j)
            #pragma unroll
            for (int q = 0; q < 4; ++q) acc[i][j][q] = 0.f;

    for (int t = 0; t < 18; ++t) {
        if (t + 1 < 18) {
            const char* src = (const char*)(g_V8 + (size_t)(t + 1) * VCHUNK_BYTES);
            uint32_t dstb = smb + SMB_V + (uint32_t)(((t + 1) % 3) * VCHUNK_BYTES);
            #pragma unroll
            for (int i = 0; i < 3; ++i) {
                int idx = tid + i * 512;
                if (idx < VCHUNK_U4) cp16(dstb + idx * 16, src + (size_t)idx * 16);
            }
            cp_commit();
            cp_wait<1>();
        } else {
            cp_wait<0>();
        }
        __syncthreads();

        const int c = (t >= NCHUNK) ? t - NCHUNK : t;
        const uint32_t vb = smb + SMB_V + (uint32_t)((t % 3) * VCHUNK_BYTES) + vlane;
        #pragma unroll
        for (int ks = 0; ks < 2; ++ks) {
            uint32_t a[2][4], b[2][4];
            uint32_t koff = (uint32_t)(c * KCH + ks * 32);
            ldsm4(a[0], hlane + koff);
            ldsm4(a[1], hlane + (uint32_t)(16 * H_STRIDE) + koff);
            ldsm4(b[0], vb + (uint32_t)(ks * 32));
            ldsm4(b[1], vb + (uint32_t)(16 * V_STRIDE) + (uint32_t)(ks * 32));
            #pragma unroll
            for (int mt = 0; mt < 2; ++mt)
                #pragma unroll
                for (int q = 0; q < 2; ++q) {
                    mma8(acc[mt][q * 2],     a[mt], b[q][0], b[q][1]);
                    mma8(acc[mt][q * 2 + 1], a[mt], b[q][2], b[q][3]);
                }
        }

        if (t == NCHUNK - 1 || t == 17) {
            const int np = (t == NCHUNK - 1) ? 0 : 1;
            int r0 = mg + (lid >> 2);
            int c0 = np * 256 + ng + (lid & 3) * 2;
            #pragma unroll
            for (int mt = 0; mt < 2; ++mt) {
                int rA = r0 + mt * 16, rB = rA + 8;
                int gA = gid[rA], gB = gid[rB];
                float kA = kern[rA], kB = kern[rB];
                #pragma unroll
                for (int nt = 0; nt < 4; ++nt) {
                    int col = c0 + nt * 8;
                    float ca = chg[col], cb = chg[col + 1];
                    if (gA >= 0) {
                        float2 z = *(const float2*)(Z_all + (size_t)gA * D + col);
                        float2 o;
                        o.x = z.x + kA * (ca + acc[mt][nt][0] * INV256);
                        o.y = z.y + kA * (cb + acc[mt][nt][1] * INV256);
                        *(float2*)(out + (size_t)gA * D + col) = o;
                    }
                    if (gB >= 0) {
                        float2 z = *(const float2*)(Z_all + (size_t)gB * D + col);
                        float2 o;
                        o.x = z.x + kB * (ca + acc[mt][nt][2] * INV256);
                        o.y = z.y + kB * (cb + acc[mt][nt][3] * INV256);
                        *(float2*)(out + (size_t)gB * D + col) = o;
                    }
                    if (np == 0) {
                        acc[mt][nt][0] = 0.f; acc[mt][nt][1] = 0.f;
                        acc[mt][nt][2] = 0.f; acc[mt][nt][3] = 0.f;
                    }
                }
            }
        }
    }
}

// ===================== launch =====================
extern "C" void kernel_launch(void* const* d_in, const int* in_sizes, int n_in,
                              void* d_out, int out_size) {
    const float* Z_all  = (const float*)d_in[0];
    const float* U      = (const float*)d_in[1];
    const float* V      = (const float*)d_in[2];
    const float* zmu    = (const float*)d_in[3];
    const float* xc     = (const float*)d_in[4];
    const int*   choice = (const int*)  d_in[5];
    float*       out    = (float*)d_out;
    const int Nc = in_sizes[5];

    if ((size_t)Nc * D != (size_t)in_sizes[0]) {
        cudaMemcpyAsync(d_out, Z_all, (size_t)in_sizes[0] * sizeof(float),
                        cudaMemcpyDeviceToDevice, 0);
    }

    prep_kernel<<<369, 256>>>(U, V, zmu, xc);

    cudaFuncSetAttribute(kernelA, cudaFuncAttributeMaxDynamicSharedMemorySize, SMA_TOTAL);
    cudaFuncSetAttribute(kernelB, cudaFuncAttributeMaxDynamicSharedMemorySize, SMB_TOTAL);
    int nA = (Nc + MROWS - 1) / MROWS;
    int nB = (Nc + MB - 1) / MB;
    kernelA<<<nA, NTHREADS, SMA_TOTAL>>>(Z_all, choice, Nc);
    kernelB<<<nB, NTHREADS, SMB_TOTAL>>>(Z_all, choice, out, Nc);
}

// round 10
// speedup vs baseline: 1.1146x; 1.1002x over previous
#include <cuda_runtime.h>
#include <cuda_bf16.h>
#include <cuda_fp8.h>
#include <math.h>
#include <stdint.h>

#define D        512
#define KK       32
#define PP       528
#define MB       64                // rows per CTA
#define KCH      64
#define NCHUNK   9
#define NTHREADS 512

#define H_STRIDE 592               // /16 odd
#define ZQ_STRIDE 272              // 128 bf16 + pad
#define V_STRIDE 80
#define U_STRIDE 80
#define VCHUNK_BYTES (256 * V_STRIDE)   // 20480
#define VCHUNK_U4    1280
#define UQ_BYTES  (128 * U_STRIDE)      // 10240

// ---------- fused kernel smem (95040B -> 2 CTAs/SM) ----------
#define SM_GID   0                 // 64 int
#define SM_KERN  256               // 64 f
#define SM_CHG   512               // 512 f
#define SM_ZMU   2560              // 512 f
#define SM_LUT   4608              // 1088B
#define SM_PBUF  5696              // 512 f
#define SM_COORD 7744              // 64*33*4 = 8448
#define SM_V     16192             // 2*20480 = 40960
#define SM_R     57152             // phase1: ZQ(17408)+Uq(2*10240)=37888 | phase2: H 37888
#define SM_UQ    74560             // SM_R + 17408
#define SM_TOTAL 95040

__device__ float g_change[D];
__device__ float g_zmu[D];
__device__ float g_xcU[KK];
__device__ float g_dU[KK];
__device__ __align__(16) unsigned short g_iup[544];
__device__ __align__(16) unsigned char g_Ubf[512 * U_STRIDE];
__device__ __align__(16) unsigned char g_V8[18 * VCHUNK_BYTES];

__device__ __forceinline__ uint32_t smem_u32(const void* p) {
    uint32_t a;
    asm("{ .reg .u64 t; cvta.to.shared.u64 t, %1; cvt.u32.u64 %0, t; }" : "=r"(a) : "l"(p));
    return a;
}
__device__ __forceinline__ void ldsm4(uint32_t* r, uint32_t a) {
    asm volatile("ldmatrix.sync.aligned.m8n8.x4.shared.b16 {%0,%1,%2,%3}, [%4];"
                 : "=r"(r[0]), "=r"(r[1]), "=r"(r[2]), "=r"(r[3]) : "r"(a));
}
__device__ __forceinline__ void ldsm4t(uint32_t* r, uint32_t a) {
    asm volatile("ldmatrix.sync.aligned.m8n8.x4.trans.shared.b16 {%0,%1,%2,%3}, [%4];"
                 : "=r"(r[0]), "=r"(r[1]), "=r"(r[2]), "=r"(r[3]) : "r"(a));
}
__device__ __forceinline__ void mma16816(float* c, const uint32_t* a, const uint32_t* b) {
    asm volatile("mma.sync.aligned.m16n8k16.row.col.f32.bf16.bf16.f32 "
                 "{%0,%1,%2,%3}, {%4,%5,%6,%7}, {%8,%9}, {%0,%1,%2,%3};"
                 : "+f"(c[0]), "+f"(c[1]), "+f"(c[2]), "+f"(c[3])
                 : "r"(a[0]), "r"(a[1]), "r"(a[2]), "r"(a[3]), "r"(b[0]), "r"(b[1]));
}
__device__ __forceinline__ void mma8(float* c, const uint32_t* a, uint32_t b0, uint32_t b1) {
    asm volatile("mma.sync.aligned.m16n8k32.row.col.f32.e4m3.e4m3.f32 "
                 "{%0,%1,%2,%3}, {%4,%5,%6,%7}, {%8,%9}, {%0,%1,%2,%3};"
                 : "+f"(c[0]), "+f"(c[1]), "+f"(c[2]), "+f"(c[3])
                 : "r"(a[0]), "r"(a[1]), "r"(a[2]), "r"(a[3]), "r"(b0), "r"(b1));
}
__device__ __forceinline__ uint32_t pack4_e4m3(float f0, float f1, float f2, float f3) {
    uint32_t r;
    asm("{\n\t.reg .b16 lo, hi;\n\t"
        "cvt.rn.satfinite.e4m3x2.f32 lo, %2, %1;\n\t"
        "cvt.rn.satfinite.e4m3x2.f32 hi, %4, %3;\n\t"
        "mov.b32 %0, {lo, hi};\n\t}"
        : "=r"(r) : "f"(f0), "f"(f1), "f"(f2), "f"(f3));
    return r;
}
__device__ __forceinline__ void cp16(uint32_t saddr, const void* g) {
    asm volatile("cp.async.cg.shared.global [%0], [%1], 16;" :: "r"(saddr), "l"(g));
}
__device__ __forceinline__ void cp_commit() {
    asm volatile("cp.async.commit_group;" ::: "memory");
}
template <int N>
__device__ __forceinline__ void cp_wait() {
    asm volatile("cp.async.wait_group %0;" :: "n"(N) : "memory");
}

// ===================== prep =====================
__global__ void prep_kernel(const float* __restrict__ U,
                            const float* __restrict__ V,
                            const float* __restrict__ zmu,
                            const float* __restrict__ xc) {
    int b = blockIdx.x, t = threadIdx.x;
    if (b < 288) {
        int g = b * 256 + t;
        int chunk = g >> 12;
        int rem = g & 4095;
        int n = rem >> 4;
        int k4 = (rem & 15) << 2;
        int np = chunk / NCHUNK, c = chunk - np * NCHUNK;
        int gk = c * KCH + k4;
        int gn = np * 256 + n;
        float4 v = make_float4(0.f, 0.f, 0.f, 0.f);
        if (gk < PP) v = *(const float4*)(V + (size_t)gn * PP + gk);
        uint32_t w = pack4_e4m3(v.x * 256.f, v.y * 256.f, v.z * 256.f, v.w * 256.f);
        *(uint32_t*)(g_V8 + (size_t)chunk * VCHUNK_BYTES + n * V_STRIDE + k4) = w;
        return;
    }
    if (b < 368) {
        int e = (b - 288) * 256 + t;
        int k = e / 40, n = e - k * 40;
        float v = (n < KK) ? U[k * KK + n] : 0.f;
        *(__nv_bfloat16*)(g_Ubf + k * U_STRIDE + n * 2) = __float2bfloat16(v);
        return;
    }
    __shared__ float pa[256], pb[256], sdiff[KK];
    {
        int j = t & 31, seg = t >> 5;
        float a = 0.f, bb = 0.f;
        for (int i = 0; i < 64; ++i) {
            int d = seg * 64 + i;
            float u = U[d * KK + j];
            a = fmaf(zmu[d], u, a);
            bb = fmaf(xc[d], u, bb);
        }
        pa[t] = a; pb[t] = bb;
    }
    __syncthreads();
    if (t < KK) {
        float sa = 0.f, sb = 0.f;
        for (int s = 0; s < 8; ++s) { sa += pa[s * 32 + t]; sb += pb[s * 32 + t]; }
        g_xcU[t] = sb;
        g_dU[t]  = sb - sa;
        sdiff[t] = sb - sa;
    }
    __syncthreads();
    for (int d = t; d < D; d += 256) {
        float s = 0.f;
        for (int j = 0; j < KK; ++j) s = fmaf(sdiff[j], U[d * KK + j], s);
        g_change[d] = xc[d] - zmu[d] - s;
        g_zmu[d] = zmu[d];
    }
    for (int p = t; p < 544; p += 256) {
        unsigned short v = 0;
        if (p < PP) {
            int i = 0, base = 0;
            while (base + (KK - i) <= p) { base += KK - i; ++i; }
            int j = i + (p - base);
            v = (unsigned short)(i | (j << 8));
        }
        g_iup[p] = v;
    }
}

// ===================== fused main kernel (M=64, occ 2) ==========
__global__ __launch_bounds__(NTHREADS, 2)
void glayer_fused(const float* __restrict__ Z_all,
                  const int*   __restrict__ choice,
                  float*       __restrict__ out,
                  int Nc) {
    extern __shared__ __align__(16) char sm[];
    const uint32_t smb = smem_u32(sm);
    int*   gid    = (int*)(sm + SM_GID);
    float* kern   = (float*)(sm + SM_KERN);
    float* chg    = (float*)(sm + SM_CHG);
    float* zmus   = (float*)(sm + SM_ZMU);
    float* pbuf   = (float*)(sm + SM_PBUF);
    float* coords = (float*)(sm + SM_COORD);

    const int tid = threadIdx.x;
    const int wid = tid >> 5;
    const int lid = tid & 31;
    const int n0  = blockIdx.x * MB;

    // V chunk 0 (group) + U quarter 0 (group) async copies up front
    {
        const char* vsrc = (const char*)g_V8;
        cp16(smb + SM_V + tid * 16, vsrc + (size_t)tid * 16);
        if (tid < VCHUNK_U4 - 512) {
            cp16(smb + SM_V + (tid + 512) * 16, vsrc + (size_t)(tid + 512) * 16);
            if (tid < VCHUNK_U4 - 1024)
                cp16(smb + SM_V + (tid + 1024) * 16, vsrc + (size_t)(tid + 1024) * 16);
        }
        cp_commit();
        const char* usrc = (const char*)g_Ubf;
        if (tid < UQ_BYTES / 16) cp16(smb + SM_UQ + tid * 16, usrc + (size_t)tid * 16);
        if (tid < UQ_BYTES / 16 - 512)
            cp16(smb + SM_UQ + (tid + 512) * 16, usrc + (size_t)(tid + 512) * 16);
        cp_commit();
    }

    if (tid < MB) {
        int n = n0 + tid;
        gid[tid] = (n < Nc) ? choice[n] : -1;
    }
    chg[tid]  = g_change[tid];
    zmus[tid] = g_zmu[tid];
    if (tid < 136) ((uint2*)(sm + SM_LUT))[tid] = ((const uint2*)g_iup)[tid];
    __syncthreads();

    // ---- phase 1: gather in 4 k-quarters + ZU mma ----
    const int r  = tid >> 3, s8 = tid & 7;          // 8 threads/row
    const int g  = gid[r];
    const float4* zrowg = (const float4*)(Z_all + (size_t)(g < 0 ? 0 : g) * D) + s8 * 4;
    char* zrow = sm + SM_R + r * ZQ_STRIDE + s8 * 32;

    // ZU warp assignment (warps 0..7)
    const int zr0 = (wid & 3) * 16;
    const int zch = (wid >> 2) & 1;                 // col half (16 cols)
    const uint32_t zbase = smb + SM_R + (uint32_t)(zr0 + (lid & 15)) * ZQ_STRIDE +
                           (uint32_t)((lid >> 4) * 16);
    const uint32_t ulane = (uint32_t)((lid & 7) + 8 * ((lid >> 3) & 1)) * U_STRIDE +
                           (uint32_t)(zch * 16 + 8 * (lid >> 4)) * 2;

    float zu[2][4];
    #pragma unroll
    for (int i = 0; i < 2; ++i)
        #pragma unroll
        for (int j = 0; j < 4; ++j) zu[i][j] = 0.f;

    float accn = 0.f;
    for (int q = 0; q < 4; ++q) {
        // gather this quarter: 4 float4 per thread
        #pragma unroll
        for (int i = 0; i < 4; ++i) {
            float4 z = make_float4(0.f, 0.f, 0.f, 0.f);
            if (g >= 0) z = zrowg[q * 32 + i];
            int d0 = q * 128 + s8 * 16 + i * 4;
            float a0 = z.x - zmus[d0], a1 = z.y - zmus[d0 + 1];
            float a2 = z.z - zmus[d0 + 2], a3 = z.w - zmus[d0 + 3];
            accn = fmaf(a0, a0, fmaf(a1, a1, fmaf(a2, a2, fmaf(a3, a3, accn))));
            __nv_bfloat162 p0 = __floats2bfloat162_rn(z.x, z.y);
            __nv_bfloat162 p1 = __floats2bfloat162_rn(z.z, z.w);
            *(uint32_t*)(zrow + i * 8)     = *(uint32_t*)&p0;
            *(uint32_t*)(zrow + i * 8 + 4) = *(uint32_t*)&p1;
        }
        if (q == 3) pbuf[tid] = accn;
        // stage next U quarter
        if (q < 3) {
            const char* usrc = (const char*)g_Ubf + (size_t)(q + 1) * UQ_BYTES;
            uint32_t ud = smb + SM_UQ + (uint32_t)(((q + 1) & 1) * UQ_BYTES);
            if (tid < UQ_BYTES / 16) cp16(ud + tid * 16, usrc + (size_t)tid * 16);
            if (tid < UQ_BYTES / 16 - 512)
                cp16(ud + (tid + 512) * 16, usrc + (size_t)(tid + 512) * 16);
            cp_commit();
            cp_wait<1>();
        } else {
            cp_wait<0>();
        }
        __syncthreads();
        if (wid < 8) {
            uint32_t ub = smb + SM_UQ + (uint32_t)((q & 1) * UQ_BYTES) + ulane;
            #pragma unroll
            for (int ks = 0; ks < 8; ++ks) {
                uint32_t a[4], b[4];
                ldsm4(a, zbase + (uint32_t)(ks * 32));
                ldsm4t(b, ub + (uint32_t)(ks * 16) * U_STRIDE);
                mma16816(zu[0], a, b);
                mma16816(zu[1], a, b + 2);
            }
        }
        __syncthreads();
    }

    // coords = ZU - xcU
    if (wid < 8) {
        int r0 = zr0 + (lid >> 2);
        int c0 = (lid & 3) * 2;
        #pragma unroll
        for (int nt = 0; nt < 2; ++nt) {
            int c = zch * 16 + nt * 8 + c0;
            coords[r0 * 33 + c]           = zu[nt][0] - g_xcU[c];
            coords[r0 * 33 + c + 1]       = zu[nt][1] - g_xcU[c + 1];
            coords[(r0 + 8) * 33 + c]     = zu[nt][2] - g_xcU[c];
            coords[(r0 + 8) * 33 + c + 1] = zu[nt][3] - g_xcU[c + 1];
        }
    }
    __syncthreads();

    // ---- secant (threads 0..63) || H build (warps 2..15) ----
    if (tid < MB) {
        const float* cr = coords + tid * 33;
        float un = 0.f;
        #pragma unroll
        for (int j = 0; j < KK; ++j) {
            float v = cr[j] + g_dU[j];
            un = fmaf(v, v, un);
        }
        float zn = 0.f;
        #pragma unroll
        for (int k = 0; k < 8; ++k) zn += pbuf[tid * 8 + k];
        float C = zn - un;
        float E = __expf(-0.01f * un);
        float x_m2 = C * 0.999f;
        float x_m1 = C;
        bool done = false;
        for (int it = 0; it < 100; ++it) {
            if (done) break;
            float t1 = 1.f - E * __expf(-0.01f * x_m1);
            float f1 = t1 * t1 * x_m1 - C;
            float t2 = 1.f - E * __expf(-0.01f * x_m2);
            float f2 = t2 * t2 * x_m2 - C;
            float fd = f1 - f2;
            if (fabsf(fd) < 1e-6f) fd = (fd >= 0.f) ? 1e-6f : -1e-6f;
            float x = x_m1 - f1 * (x_m1 - x_m2) / fd;
            float step = fabsf(x - x_m1);
            x_m2 = x_m1;
            x_m1 = x;
            done = (step < 1e-6f);
        }
        kern[tid] = __expf(-0.01f * (un + x_m1));
    }
    if (wid >= 2) {
        const unsigned short* lut = (const unsigned short*)(sm + SM_LUT);
        for (int m = wid - 2; m < MB; m += 14) {
            const float* cr = coords + m * 33;
            char* hrow = sm + SM_R + m * H_STRIDE;
            #pragma unroll
            for (int it = 0; it < 5; ++it) {
                int gp = lid + it * 32;
                if (gp < 144) {
                    int p = gp * 4;
                    uint32_t w = 0;
                    if (p < PP) {
                        uint2 lu = *(const uint2*)(lut + p);
                        int a0 = lu.x & 255, b0 = (lu.x >> 8) & 255;
                        int a1 = (lu.x >> 16) & 255, b1 = (lu.x >> 24) & 255;
                        int a2 = lu.y & 255, b2 = (lu.y >> 8) & 255;
                        int a3 = (lu.y >> 16) & 255, b3 = (lu.y >> 24) & 255;
                        w = pack4_e4m3(cr[a0] * cr[b0], cr[a1] * cr[b1],
                                       cr[a2] * cr[b2], cr[a3] * cr[b3]);
                    }
                    *(uint32_t*)(hrow + p) = w;
                }
            }
        }
    }

    // ---- main GEMM: 18 flat chunks, 2-stage V double buffer ----
    const int mg = (wid >> 3) * 32;
    const int ng = (wid & 7) * 32;
    const uint32_t hlane = smb + SM_R + (uint32_t)(mg + (lid & 15)) * H_STRIDE +
                           (uint32_t)((lid >> 4) * 16);
    const uint32_t vlane = (uint32_t)(ng + (lid & 7) + 8 * ((lid >> 4) & 1)) * V_STRIDE +
                           (uint32_t)(((lid >> 3) & 1) * 16);
    const float INV256 = 0.00390625f;

    float acc[2][4][4];
    #pragma unroll
    for (int i = 0; i < 2; ++i)
        #pragma unroll
        for (int j = 0; j < 4; ++j)
            #pragma unroll
            for (int q = 0; q < 4; ++q) acc[i][j][q] = 0.f;

    for (int t = 0; t < 18; ++t) {
        cp_wait<0>();          // chunk t's copy complete (issued last iter)
        __syncthreads();       // also orders H build / prior compute
        if (t + 1 < 18) {      // overlap copy t+1 with compute t
            const char* src = (const char*)(g_V8 + (size_t)(t + 1) * VCHUNK_BYTES);
            uint32_t dstb = smb + SM_V + (uint32_t)(((t + 1) & 1) * VCHUNK_BYTES);
            cp16(dstb + tid * 16, src + (size_t)tid * 16);
            if (tid < VCHUNK_U4 - 512) {
                cp16(dstb + (tid + 512) * 16, src + (size_t)(tid + 512) * 16);
                if (tid < VCHUNK_U4 - 1024)
                    cp16(dstb + (tid + 1024) * 16, src + (size_t)(tid + 1024) * 16);
            }
            cp_commit();
        }

        const int c = (t >= NCHUNK) ? t - NCHUNK : t;
        const uint32_t vb = smb + SM_V + (uint32_t)((t & 1) * VCHUNK_BYTES) + vlane;
        #pragma unroll
        for (int ks = 0; ks < 2; ++ks) {
            uint32_t a[2][4], b[2][4];
            uint32_t koff = (uint32_t)(c * KCH + ks * 32);
            ldsm4(a[0], hlane + koff);
            ldsm4(a[1], hlane + (uint32_t)(16 * H_STRIDE) + koff);
            ldsm4(b[0], vb + (uint32_t)(ks * 32));
            ldsm4(b[1], vb + (uint32_t)(16 * V_STRIDE) + (uint32_t)(ks * 32));
            #pragma unroll
            for (int mt = 0; mt < 2; ++mt)
                #pragma unroll
                for (int q = 0; q < 2; ++q) {
                    mma8(acc[mt][q * 2],     a[mt], b[q][0], b[q][1]);
                    mma8(acc[mt][q * 2 + 1], a[mt], b[q][2], b[q][3]);
                }
        }

        if (t == NCHUNK - 1 || t == 17) {
            const int np = (t == NCHUNK - 1) ? 0 : 1;
            int r0 = mg + (lid >> 2);
            int c0 = np * 256 + ng + (lid & 3) * 2;
            #pragma unroll
            for (int mt = 0; mt < 2; ++mt) {
                int rA = r0 + mt * 16, rB = rA + 8;
                int gA = gid[rA], gB = gid[rB];
                float kA = kern[rA], kB = kern[rB];
                #pragma unroll
                for (int nt = 0; nt < 4; ++nt) {
                    int col = c0 + nt * 8;
                    float ca = chg[col], cb = chg[col + 1];
                    if (gA >= 0) {
                        float2 z = *(const float2*)(Z_all + (size_t)gA * D + col);
                        float2 o;
                        o.x = z.x + kA * (ca + acc[mt][nt][0] * INV256);
                        o.y = z.y + kA * (cb + acc[mt][nt][1] * INV256);
                        *(float2*)(out + (size_t)gA * D + col) = o;
                    }
                    if (gB >= 0) {
                        float2 z = *(const float2*)(Z_all + (size_t)gB * D + col);
                        float2 o;
                        o.x = z.x + kB * (ca + acc[mt][nt][2] * INV256);
                        o.y = z.y + kB * (cb + acc[mt][nt][3] * INV256);
                        *(float2*)(out + (size_t)gB * D + col) = o;
                    }
                    if (np == 0) {
                        acc[mt][nt][0] = 0.f; acc[mt][nt][1] = 0.f;
                        acc[mt][nt][2] = 0.f; acc[mt][nt][3] = 0.f;
                    }
                }
            }
        }
    }
}

// ===================== launch =====================
extern "C" void kernel_launch(void* const* d_in, const int* in_sizes, int n_in,
                              void* d_out, int out_size) {
    const float* Z_all  = (const float*)d_in[0];
    const float* U      = (const float*)d_in[1];
    const float* V      = (const float*)d_in[2];
    const float* zmu    = (const float*)d_in[3];
    const float* xc     = (const float*)d_in[4];
    const int*   choice = (const int*)  d_in[5];
    float*       out    = (float*)d_out;
    const int Nc = in_sizes[5];

    if ((size_t)Nc * D != (size_t)in_sizes[0]) {
        cudaMemcpyAsync(d_out, Z_all, (size_t)in_sizes[0] * sizeof(float),
                        cudaMemcpyDeviceToDevice, 0);
    }

    prep_kernel<<<369, 256>>>(U, V, zmu, xc);

    cudaFuncSetAttribute(glayer_fused, cudaFuncAttributeMaxDynamicSharedMemorySize, SM_TOTAL);
    int nblocks = (Nc + MB - 1) / MB;
    glayer_fused<<<nblocks, NTHREADS, SM_TOTAL>>>(Z_all, choice, out, Nc);
}

// round 11
// speedup vs baseline: 1.1876x; 1.0655x over previous
#include <cuda_runtime.h>
#include <cuda_bf16.h>
#include <cuda_fp8.h>
#include <math.h>
#include <stdint.h>

#define D        512
#define KK       32
#define PP       528
#define MB       64                // rows per CTA
#define KCH      64
#define NCHUNK   9
#define NTHREADS 512

#define H_STRIDE 592               // /16 odd
#define ZQ_STRIDE 272              // 128 bf16 + pad
#define U_STRIDE 80
#define UQ_BYTES  (128 * U_STRIDE)      // 10240

// ---------- fused kernel smem (54080B -> 2 CTAs/SM with big L1 carveout) ----
#define SM_GID   0                 // 64 int
#define SM_KERN  256               // 64 f
#define SM_CHG   512               // 512 f
#define SM_ZMU   2560              // 512 f
#define SM_LUT   4608              // 1088B
#define SM_PBUF  5696              // 512 f
#define SM_COORD 7744              // 64*33*4 = 8448
#define SM_R     16192             // phase1: ZQ(17408) + UQ(2*10240) | phase2: H(37888)
#define SM_UQ    33600             // SM_R + 17408
#define SM_TOTAL 54080

__device__ float g_change[D];
__device__ float g_zmu[D];
__device__ float g_xcU[KK];
__device__ float g_dU[KK];
__device__ __align__(16) unsigned short g_iup[544];
__device__ __align__(16) unsigned char g_Ubf[512 * U_STRIDE];
// V in mma-fragment order: [chunk t(18)][ngrp(8)][ks(2)][q(2)][lane(32)][j(4) u32]
__device__ __align__(16) unsigned char g_Vfrag[18 * 16384];   // 288KB

__device__ __forceinline__ uint32_t smem_u32(const void* p) {
    uint32_t a;
    asm("{ .reg .u64 t; cvta.to.shared.u64 t, %1; cvt.u32.u64 %0, t; }" : "=r"(a) : "l"(p));
    return a;
}
__device__ __forceinline__ void ldsm4(uint32_t* r, uint32_t a) {
    asm volatile("ldmatrix.sync.aligned.m8n8.x4.shared.b16 {%0,%1,%2,%3}, [%4];"
                 : "=r"(r[0]), "=r"(r[1]), "=r"(r[2]), "=r"(r[3]) : "r"(a));
}
__device__ __forceinline__ void ldsm4t(uint32_t* r, uint32_t a) {
    asm volatile("ldmatrix.sync.aligned.m8n8.x4.trans.shared.b16 {%0,%1,%2,%3}, [%4];"
                 : "=r"(r[0]), "=r"(r[1]), "=r"(r[2]), "=r"(r[3]) : "r"(a));
}
__device__ __forceinline__ void mma16816(float* c, const uint32_t* a, const uint32_t* b) {
    asm volatile("mma.sync.aligned.m16n8k16.row.col.f32.bf16.bf16.f32 "
                 "{%0,%1,%2,%3}, {%4,%5,%6,%7}, {%8,%9}, {%0,%1,%2,%3};"
                 : "+f"(c[0]), "+f"(c[1]), "+f"(c[2]), "+f"(c[3])
                 : "r"(a[0]), "r"(a[1]), "r"(a[2]), "r"(a[3]), "r"(b[0]), "r"(b[1]));
}
__device__ __forceinline__ void mma8(float* c, const uint32_t* a, uint32_t b0, uint32_t b1) {
    asm volatile("mma.sync.aligned.m16n8k32.row.col.f32.e4m3.e4m3.f32 "
                 "{%0,%1,%2,%3}, {%4,%5,%6,%7}, {%8,%9}, {%0,%1,%2,%3};"
                 : "+f"(c[0]), "+f"(c[1]), "+f"(c[2]), "+f"(c[3])
                 : "r"(a[0]), "r"(a[1]), "r"(a[2]), "r"(a[3]), "r"(b0), "r"(b1));
}
__device__ __forceinline__ uint32_t pack4_e4m3(float f0, float f1, float f2, float f3) {
    uint32_t r;
    asm("{\n\t.reg .b16 lo, hi;\n\t"
        "cvt.rn.satfinite.e4m3x2.f32 lo, %2, %1;\n\t"
        "cvt.rn.satfinite.e4m3x2.f32 hi, %4, %3;\n\t"
        "mov.b32 %0, {lo, hi};\n\t}"
        : "=r"(r) : "f"(f0), "f"(f1), "f"(f2), "f"(f3));
    return r;
}
__device__ __forceinline__ void cp16(uint32_t saddr, const void* g) {
    asm volatile("cp.async.cg.shared.global [%0], [%1], 16;" :: "r"(saddr), "l"(g));
}
__device__ __forceinline__ void cp_commit() {
    asm volatile("cp.async.commit_group;" ::: "memory");
}
template <int N>
__device__ __forceinline__ void cp_wait() {
    asm volatile("cp.async.wait_group %0;" :: "n"(N) : "memory");
}

// ===================== prep =====================
// blocks 0..287: V -> fragment-order fp8*256 (replicates the ldsm lane math)
// blocks 288..367: U -> bf16 [512][40]
// block  368: consts
__global__ void prep_kernel(const float* __restrict__ U,
                            const float* __restrict__ V,
                            const float* __restrict__ zmu,
                            const float* __restrict__ xc) {
    int b = blockIdx.x, t = threadIdx.x;
    if (b < 288) {
        int idx = b * 256 + t;                 // one 4-byte fragment word
        int j    = idx & 3;
        int l    = (idx >> 2) & 31;
        int q    = (idx >> 7) & 1;
        int ks   = (idx >> 8) & 1;
        int ngrp = (idx >> 9) & 7;
        int tt   = idx >> 12;                  // 0..17
        // ldsm lane index that would have supplied this word
        int i    = 8 * j + (l >> 2);
        int nl   = ngrp * 32 + q * 16 + (i & 7) + 8 * ((i >> 4) & 1);
        int koff = ((i >> 3) & 1) * 16 + ks * 32 + (l & 3) * 4;
        int c  = tt % NCHUNK, np = tt / NCHUNK;
        int d  = np * 256 + nl;
        int gk = c * KCH + koff;
        float4 v = make_float4(0.f, 0.f, 0.f, 0.f);
        if (gk < PP) v = *(const float4*)(V + (size_t)d * PP + gk);
        *(uint32_t*)(g_Vfrag + (size_t)idx * 4) =
            pack4_e4m3(v.x * 256.f, v.y * 256.f, v.z * 256.f, v.w * 256.f);
        return;
    }
    if (b < 368) {
        int e = (b - 288) * 256 + t;
        int k = e / 40, n = e - k * 40;
        float v = (n < KK) ? U[k * KK + n] : 0.f;
        *(__nv_bfloat16*)(g_Ubf + k * U_STRIDE + n * 2) = __float2bfloat16(v);
        return;
    }
    __shared__ float pa[256], pb[256], sdiff[KK];
    {
        int j = t & 31, seg = t >> 5;
        float a = 0.f, bb = 0.f;
        for (int i = 0; i < 64; ++i) {
            int d = seg * 64 + i;
            float u = U[d * KK + j];
            a = fmaf(zmu[d], u, a);
            bb = fmaf(xc[d], u, bb);
        }
        pa[t] = a; pb[t] = bb;
    }
    __syncthreads();
    if (t < KK) {
        float sa = 0.f, sb = 0.f;
        for (int s = 0; s < 8; ++s) { sa += pa[s * 32 + t]; sb += pb[s * 32 + t]; }
        g_xcU[t] = sb;
        g_dU[t]  = sb - sa;
        sdiff[t] = sb - sa;
    }
    __syncthreads();
    for (int d = t; d < D; d += 256) {
        float s = 0.f;
        for (int j = 0; j < KK; ++j) s = fmaf(sdiff[j], U[d * KK + j], s);
        g_change[d] = xc[d] - zmu[d] - s;
        g_zmu[d] = zmu[d];
    }
    for (int p = t; p < 544; p += 256) {
        unsigned short v = 0;
        if (p < PP) {
            int i = 0, base = 0;
            while (base + (KK - i) <= p) { base += KK - i; ++i; }
            int j = i + (p - base);
            v = (unsigned short)(i | (j << 8));
        }
        g_iup[p] = v;
    }
}

// ===================== fused main kernel (M=64, occ 2) ==========
__global__ __launch_bounds__(NTHREADS, 2)
void glayer_fused(const float* __restrict__ Z_all,
                  const int*   __restrict__ choice,
                  float*       __restrict__ out,
                  int Nc) {
    extern __shared__ __align__(16) char sm[];
    const uint32_t smb = smem_u32(sm);
    int*   gid    = (int*)(sm + SM_GID);
    float* kern   = (float*)(sm + SM_KERN);
    float* chg    = (float*)(sm + SM_CHG);
    float* zmus   = (float*)(sm + SM_ZMU);
    float* pbuf   = (float*)(sm + SM_PBUF);
    float* coords = (float*)(sm + SM_COORD);

    const int tid = threadIdx.x;
    const int wid = tid >> 5;
    const int lid = tid & 31;
    const int n0  = blockIdx.x * MB;

    // U quarter 0 async copy up front
    {
        const char* usrc = (const char*)g_Ubf;
        if (tid < UQ_BYTES / 16) cp16(smb + SM_UQ + tid * 16, usrc + (size_t)tid * 16);
        if (tid < UQ_BYTES / 16 - 512)
            cp16(smb + SM_UQ + (tid + 512) * 16, usrc + (size_t)(tid + 512) * 16);
        cp_commit();
    }

    if (tid < MB) {
        int n = n0 + tid;
        gid[tid] = (n < Nc) ? choice[n] : -1;
    }
    chg[tid]  = g_change[tid];
    zmus[tid] = g_zmu[tid];
    if (tid < 136) ((uint2*)(sm + SM_LUT))[tid] = ((const uint2*)g_iup)[tid];
    __syncthreads();

    // ---- phase 1: gather in 4 k-quarters + ZU mma ----
    const int r  = tid >> 3, s8 = tid & 7;          // 8 threads/row
    const int g  = gid[r];
    const float4* zrowg = (const float4*)(Z_all + (size_t)(g < 0 ? 0 : g) * D) + s8 * 4;
    char* zrow = sm + SM_R + r * ZQ_STRIDE + s8 * 32;

    const int zr0 = (wid & 3) * 16;
    const int zch = (wid >> 2) & 1;
    const uint32_t zbase = smb + SM_R + (uint32_t)(zr0 + (lid & 15)) * ZQ_STRIDE +
                           (uint32_t)((lid >> 4) * 16);
    const uint32_t ulane = (uint32_t)((lid & 7) + 8 * ((lid >> 3) & 1)) * U_STRIDE +
                           (uint32_t)(zch * 16 + 8 * (lid >> 4)) * 2;

    float zu[2][4];
    #pragma unroll
    for (int i = 0; i < 2; ++i)
        #pragma unroll
        for (int j = 0; j < 4; ++j) zu[i][j] = 0.f;

    float accn = 0.f;
    for (int q = 0; q < 4; ++q) {
        #pragma unroll
        for (int i = 0; i < 4; ++i) {
            float4 z = make_float4(0.f, 0.f, 0.f, 0.f);
            if (g >= 0) z = zrowg[q * 32 + i];
            int d0 = q * 128 + s8 * 16 + i * 4;
            float a0 = z.x - zmus[d0], a1 = z.y - zmus[d0 + 1];
            float a2 = z.z - zmus[d0 + 2], a3 = z.w - zmus[d0 + 3];
            accn = fmaf(a0, a0, fmaf(a1, a1, fmaf(a2, a2, fmaf(a3, a3, accn))));
            __nv_bfloat162 p0 = __floats2bfloat162_rn(z.x, z.y);
            __nv_bfloat162 p1 = __floats2bfloat162_rn(z.z, z.w);
            *(uint32_t*)(zrow + i * 8)     = *(uint32_t*)&p0;
            *(uint32_t*)(zrow + i * 8 + 4) = *(uint32_t*)&p1;
        }
        if (q == 3) pbuf[tid] = accn;
        if (q < 3) {
            const char* usrc = (const char*)g_Ubf + (size_t)(q + 1) * UQ_BYTES;
            uint32_t ud = smb + SM_UQ + (uint32_t)(((q + 1) & 1) * UQ_BYTES);
            if (tid < UQ_BYTES / 16) cp16(ud + tid * 16, usrc + (size_t)tid * 16);
            if (tid < UQ_BYTES / 16 - 512)
                cp16(ud + (tid + 512) * 16, usrc + (size_t)(tid + 512) * 16);
            cp_commit();
            cp_wait<1>();
        } else {
            cp_wait<0>();
        }
        __syncthreads();
        if (wid < 8) {
            uint32_t ub = smb + SM_UQ + (uint32_t)((q & 1) * UQ_BYTES) + ulane;
            #pragma unroll
            for (int ks = 0; ks < 8; ++ks) {
                uint32_t a[4], b[4];
                ldsm4(a, zbase + (uint32_t)(ks * 32));
                ldsm4t(b, ub + (uint32_t)(ks * 16) * U_STRIDE);
                mma16816(zu[0], a, b);
                mma16816(zu[1], a, b + 2);
            }
        }
        __syncthreads();
    }

    // coords = ZU - xcU
    if (wid < 8) {
        int r0 = zr0 + (lid >> 2);
        int c0 = (lid & 3) * 2;
        #pragma unroll
        for (int nt = 0; nt < 2; ++nt) {
            int c = zch * 16 + nt * 8 + c0;
            coords[r0 * 33 + c]           = zu[nt][0] - g_xcU[c];
            coords[r0 * 33 + c + 1]       = zu[nt][1] - g_xcU[c + 1];
            coords[(r0 + 8) * 33 + c]     = zu[nt][2] - g_xcU[c];
            coords[(r0 + 8) * 33 + c + 1] = zu[nt][3] - g_xcU[c + 1];
        }
    }
    __syncthreads();

    // ---- secant (threads 0..63) || H build (warps 2..15) ----
    if (tid < MB) {
        const float* cr = coords + tid * 33;
        float un = 0.f;
        #pragma unroll
        for (int j = 0; j < KK; ++j) {
            float v = cr[j] + g_dU[j];
            un = fmaf(v, v, un);
        }
        float zn = 0.f;
        #pragma unroll
        for (int k = 0; k < 8; ++k) zn += pbuf[tid * 8 + k];
        float C = zn - un;
        float E = __expf(-0.01f * un);
        float x_m2 = C * 0.999f;
        float x_m1 = C;
        bool done = false;
        for (int it = 0; it < 100; ++it) {
            if (done) break;
            float t1 = 1.f - E * __expf(-0.01f * x_m1);
            float f1 = t1 * t1 * x_m1 - C;
            float t2 = 1.f - E * __expf(-0.01f * x_m2);
            float f2 = t2 * t2 * x_m2 - C;
            float fd = f1 - f2;
            if (fabsf(fd) < 1e-6f) fd = (fd >= 0.f) ? 1e-6f : -1e-6f;
            float x = x_m1 - f1 * (x_m1 - x_m2) / fd;
            float step = fabsf(x - x_m1);
            x_m2 = x_m1;
            x_m1 = x;
            done = (step < 1e-6f);
        }
        kern[tid] = __expf(-0.01f * (un + x_m1));
    }
    if (wid >= 2) {
        const unsigned short* lut = (const unsigned short*)(sm + SM_LUT);
        for (int m = wid - 2; m < MB; m += 14) {
            const float* cr = coords + m * 33;
            char* hrow = sm + SM_R + m * H_STRIDE;
            #pragma unroll
            for (int it = 0; it < 5; ++it) {
                int gp = lid + it * 32;
                if (gp < 144) {
                    int p = gp * 4;
                    uint32_t w = 0;
                    if (p < PP) {
                        uint2 lu = *(const uint2*)(lut + p);
                        int a0 = lu.x & 255, b0 = (lu.x >> 8) & 255;
                        int a1 = (lu.x >> 16) & 255, b1 = (lu.x >> 24) & 255;
                        int a2 = lu.y & 255, b2 = (lu.y >> 8) & 255;
                        int a3 = (lu.y >> 16) & 255, b3 = (lu.y >> 24) & 255;
                        w = pack4_e4m3(cr[a0] * cr[b0], cr[a1] * cr[b1],
                                       cr[a2] * cr[b2], cr[a3] * cr[b3]);
                    }
                    *(uint32_t*)(hrow + p) = w;
                }
            }
        }
    }
    __syncthreads();    // H visible to all warps; last barrier of the kernel

    // ---- main GEMM: 18 chunks, barrier-free streaming (b via direct LDG) ----
    const int mg = (wid >> 3) * 32;
    const uint32_t hlane = smb + SM_R + (uint32_t)(mg + (lid & 15)) * H_STRIDE +
                           (uint32_t)((lid >> 4) * 16);
    const char* vfw = (const char*)g_Vfrag + (uint32_t)((wid & 7) * 2048 + lid * 16);
    const float INV256 = 0.00390625f;

    float acc[2][4][4];
    #pragma unroll
    for (int i = 0; i < 2; ++i)
        #pragma unroll
        for (int j = 0; j < 4; ++j)
            #pragma unroll
            for (int q = 0; q < 4; ++q) acc[i][j][q] = 0.f;

    for (int t = 0; t < 18; ++t) {
        const uint4* vp = (const uint4*)(vfw + (size_t)t * 16384);
        uint4 b00 = vp[0];      // ks0 q0
        uint4 b01 = vp[32];     // ks0 q1
        uint4 b10 = vp[64];     // ks1 q0
        uint4 b11 = vp[96];     // ks1 q1

        const int c = (t >= NCHUNK) ? t - NCHUNK : t;
        const uint32_t koff = (uint32_t)(c * KCH);
        uint32_t a0[4], a1[4];
        // ks = 0
        ldsm4(a0, hlane + koff);
        ldsm4(a1, hlane + (uint32_t)(16 * H_STRIDE) + koff);
        mma8(acc[0][0], a0, b00.x, b00.y);
        mma8(acc[0][1], a0, b00.z, b00.w);
        mma8(acc[0][2], a0, b01.x, b01.y);
        mma8(acc[0][3], a0, b01.z, b01.w);
        mma8(acc[1][0], a1, b00.x, b00.y);
        mma8(acc[1][1], a1, b00.z, b00.w);
        mma8(acc[1][2], a1, b01.x, b01.y);
        mma8(acc[1][3], a1, b01.z, b01.w);
        // ks = 1
        ldsm4(a0, hlane + koff + 32);
        ldsm4(a1, hlane + (uint32_t)(16 * H_STRIDE) + koff + 32);
        mma8(acc[0][0], a0, b10.x, b10.y);
        mma8(acc[0][1], a0, b10.z, b10.w);
        mma8(acc[0][2], a0, b11.x, b11.y);
        mma8(acc[0][3], a0, b11.z, b11.w);
        mma8(acc[1][0], a1, b10.x, b10.y);
        mma8(acc[1][1], a1, b10.z, b10.w);
        mma8(acc[1][2], a1, b11.x, b11.y);
        mma8(acc[1][3], a1, b11.z, b11.w);

        if (t == NCHUNK - 1 || t == 17) {
            const int np = (t == NCHUNK - 1) ? 0 : 1;
            int r0 = mg + (lid >> 2);
            int c0 = np * 256 + (wid & 7) * 32 + (lid & 3) * 2;
            #pragma unroll
            for (int mt = 0; mt < 2; ++mt) {
                int rA = r0 + mt * 16, rB = rA + 8;
                int gA = gid[rA], gB = gid[rB];
                float kA = kern[rA], kB = kern[rB];
                #pragma unroll
                for (int nt = 0; nt < 4; ++nt) {
                    int col = c0 + nt * 8;
                    float ca = chg[col], cb = chg[col + 1];
                    if (gA >= 0) {
                        float2 z = *(const float2*)(Z_all + (size_t)gA * D + col);
                        float2 o;
                        o.x = z.x + kA * (ca + acc[mt][nt][0] * INV256);
                        o.y = z.y + kA * (cb + acc[mt][nt][1] * INV256);
                        *(float2*)(out + (size_t)gA * D + col) = o;
                    }
                    if (gB >= 0) {
                        float2 z = *(const float2*)(Z_all + (size_t)gB * D + col);
                        float2 o;
                        o.x = z.x + kB * (ca + acc[mt][nt][2] * INV256);
                        o.y = z.y + kB * (cb + acc[mt][nt][3] * INV256);
                        *(float2*)(out + (size_t)gB * D + col) = o;
                    }
                    if (np == 0) {
                        acc[mt][nt][0] = 0.f; acc[mt][nt][1] = 0.f;
                        acc[mt][nt][2] = 0.f; acc[mt][nt][3] = 0.f;
                    }
                }
            }
        }
    }
}

// ===================== launch =====================
extern "C" void kernel_launch(void* const* d_in, const int* in_sizes, int n_in,
                              void* d_out, int out_size) {
    const float* Z_all  = (const float*)d_in[0];
    const float* U      = (const float*)d_in[1];
    const float* V      = (const float*)d_in[2];
    const float* zmu    = (const float*)d_in[3];
    const float* xc     = (const float*)d_in[4];
    const int*   choice = (const int*)  d_in[5];
    float*       out    = (float*)d_out;
    const int Nc = in_sizes[5];

    if ((size_t)Nc * D != (size_t)in_sizes[0]) {
        cudaMemcpyAsync(d_out, Z_all, (size_t)in_sizes[0] * sizeof(float),
                        cudaMemcpyDeviceToDevice, 0);
    }

    prep_kernel<<<369, 256>>>(U, V, zmu, xc);

    cudaFuncSetAttribute(glayer_fused, cudaFuncAttributeMaxDynamicSharedMemorySize, SM_TOTAL);
    int nblocks = (Nc + MB - 1) / MB;
    glayer_fused<<<nblocks, NTHREADS, SM_TOTAL>>>(Z_all, choice, out, Nc);
}

// round 12
// speedup vs baseline: 1.3485x; 1.1355x over previous
#include <cuda_runtime.h>
#include <cuda_bf16.h>
#include <cuda_fp16.h>
#include <cuda_fp8.h>
#include <math.h>
#include <stdint.h>

#define D        512
#define KK       32
#define PP       528
#define MB       64                // rows per CTA
#define KCH      64
#define NCHUNK   9
#define NTHREADS 512

#define H_STRIDE 592               // /16 odd
#define ZQ_STRIDE 272              // 128 bf16 + pad
#define U_STRIDE 80
#define UQ_BYTES  (128 * U_STRIDE)      // 10240
#define CT_STRIDE 65               // coordsT word stride (65 mod 32 == 1)

// ---------- fused kernel smem ----------
#define SM_GID   0                 // 64 int
#define SM_KERN  256               // 64 f
#define SM_CHG   512               // 512 f
#define SM_ZMU   2560              // 512 f
#define SM_LUT   4608              // 1088B
#define SM_PBUF  5696              // 512 f
#define SM_COORD 7744              // 32*65*4 = 8320 (coordsT)
#define SM_R     16192             // phase1: ZQ(17408)+UQ(2*10240) | phase2: H(37888)
#define SM_UQ    33600
#define SM_TOTAL 54080

__device__ float g_change[D];
__device__ float g_zmu[D];
__device__ float g_xcU[KK];
__device__ float g_dU[KK];
__device__ __align__(16) unsigned short g_iup[544];
__device__ __align__(16) unsigned char g_Ubf[512 * U_STRIDE];
// V in mma-fragment order: [tile(18)][ngrp(8)][ks(2)][q(2)][lane(32)][j(4) u32]
__device__ __align__(16) unsigned char g_Vfrag[18 * 16384];   // 288KB

__device__ __forceinline__ uint32_t smem_u32(const void* p) {
    uint32_t a;
    asm("{ .reg .u64 t; cvta.to.shared.u64 t, %1; cvt.u32.u64 %0, t; }" : "=r"(a) : "l"(p));
    return a;
}
__device__ __forceinline__ void ldsm4(uint32_t* r, uint32_t a) {
    asm volatile("ldmatrix.sync.aligned.m8n8.x4.shared.b16 {%0,%1,%2,%3}, [%4];"
                 : "=r"(r[0]), "=r"(r[1]), "=r"(r[2]), "=r"(r[3]) : "r"(a));
}
__device__ __forceinline__ void ldsm4t(uint32_t* r, uint32_t a) {
    asm volatile("ldmatrix.sync.aligned.m8n8.x4.trans.shared.b16 {%0,%1,%2,%3}, [%4];"
                 : "=r"(r[0]), "=r"(r[1]), "=r"(r[2]), "=r"(r[3]) : "r"(a));
}
__device__ __forceinline__ void mma16816(float* c, const uint32_t* a, const uint32_t* b) {
    asm volatile("mma.sync.aligned.m16n8k16.row.col.f32.bf16.bf16.f32 "
                 "{%0,%1,%2,%3}, {%4,%5,%6,%7}, {%8,%9}, {%0,%1,%2,%3};"
                 : "+f"(c[0]), "+f"(c[1]), "+f"(c[2]), "+f"(c[3])
                 : "r"(a[0]), "r"(a[1]), "r"(a[2]), "r"(a[3]), "r"(b[0]), "r"(b[1]));
}
// fp8 x fp8 -> packed fp16 accumulate
__device__ __forceinline__ void mma8h(uint32_t* c, const uint32_t* a, uint32_t b0, uint32_t b1) {
    asm volatile("mma.sync.aligned.m16n8k32.row.col.f16.e4m3.e4m3.f16 "
                 "{%0,%1}, {%2,%3,%4,%5}, {%6,%7}, {%0,%1};"
                 : "+r"(c[0]), "+r"(c[1])
                 : "r"(a[0]), "r"(a[1]), "r"(a[2]), "r"(a[3]), "r"(b0), "r"(b1));
}
__device__ __forceinline__ uint32_t pack4_e4m3(float f0, float f1, float f2, float f3) {
    uint32_t r;
    asm("{\n\t.reg .b16 lo, hi;\n\t"
        "cvt.rn.satfinite.e4m3x2.f32 lo, %2, %1;\n\t"
        "cvt.rn.satfinite.e4m3x2.f32 hi, %4, %3;\n\t"
        "mov.b32 %0, {lo, hi};\n\t}"
        : "=r"(r) : "f"(f0), "f"(f1), "f"(f2), "f"(f3));
    return r;
}
__device__ __forceinline__ void cp16(uint32_t saddr, const void* g) {
    asm volatile("cp.async.cg.shared.global [%0], [%1], 16;" :: "r"(saddr), "l"(g));
}
__device__ __forceinline__ void cp_commit() {
    asm volatile("cp.async.commit_group;" ::: "memory");
}
template <int N>
__device__ __forceinline__ void cp_wait() {
    asm volatile("cp.async.wait_group %0;" :: "n"(N) : "memory");
}

// ===================== prep (unchanged layout) =====================
__global__ void prep_kernel(const float* __restrict__ U,
                            const float* __restrict__ V,
                            const float* __restrict__ zmu,
                            const float* __restrict__ xc) {
    int b = blockIdx.x, t = threadIdx.x;
    if (b < 288) {
        int idx = b * 256 + t;
        int j    = idx & 3;
        int l    = (idx >> 2) & 31;
        int q    = (idx >> 7) & 1;
        int ks   = (idx >> 8) & 1;
        int ngrp = (idx >> 9) & 7;
        int tt   = idx >> 12;
        int i    = 8 * j + (l >> 2);
        int nl   = ngrp * 32 + q * 16 + (i & 7) + 8 * ((i >> 4) & 1);
        int koff = ((i >> 3) & 1) * 16 + ks * 32 + (l & 3) * 4;
        int c  = tt % NCHUNK, np = tt / NCHUNK;
        int d  = np * 256 + nl;
        int gk = c * KCH + koff;
        float4 v = make_float4(0.f, 0.f, 0.f, 0.f);
        if (gk < PP) v = *(const float4*)(V + (size_t)d * PP + gk);
        *(uint32_t*)(g_Vfrag + (size_t)idx * 4) =
            pack4_e4m3(v.x * 256.f, v.y * 256.f, v.z * 256.f, v.w * 256.f);
        return;
    }
    if (b < 368) {
        int e = (b - 288) * 256 + t;
        int k = e / 40, n = e - k * 40;
        float v = (n < KK) ? U[k * KK + n] : 0.f;
        *(__nv_bfloat16*)(g_Ubf + k * U_STRIDE + n * 2) = __float2bfloat16(v);
        return;
    }
    __shared__ float pa[256], pb[256], sdiff[KK];
    {
        int j = t & 31, seg = t >> 5;
        float a = 0.f, bb = 0.f;
        for (int i = 0; i < 64; ++i) {
            int d = seg * 64 + i;
            float u = U[d * KK + j];
            a = fmaf(zmu[d], u, a);
            bb = fmaf(xc[d], u, bb);
        }
        pa[t] = a; pb[t] = bb;
    }
    __syncthreads();
    if (t < KK) {
        float sa = 0.f, sb = 0.f;
        for (int s = 0; s < 8; ++s) { sa += pa[s * 32 + t]; sb += pb[s * 32 + t]; }
        g_xcU[t] = sb;
        g_dU[t]  = sb - sa;
        sdiff[t] = sb - sa;
    }
    __syncthreads();
    for (int d = t; d < D; d += 256) {
        float s = 0.f;
        for (int j = 0; j < KK; ++j) s = fmaf(sdiff[j], U[d * KK + j], s);
        g_change[d] = xc[d] - zmu[d] - s;
        g_zmu[d] = zmu[d];
    }
    for (int p = t; p < 544; p += 256) {
        unsigned short v = 0;
        if (p < PP) {
            int i = 0, base = 0;
            while (base + (KK - i) <= p) { base += KK - i; ++i; }
            int j = i + (p - base);
            v = (unsigned short)(i | (j << 8));
        }
        g_iup[p] = v;
    }
}

// ===================== fused main kernel (M=64, occ 2) ==========
__global__ __launch_bounds__(NTHREADS, 2)
void glayer_fused(const float* __restrict__ Z_all,
                  const int*   __restrict__ choice,
                  float*       __restrict__ out,
                  int Nc) {
    extern __shared__ __align__(16) char sm[];
    const uint32_t smb = smem_u32(sm);
    int*   gid    = (int*)(sm + SM_GID);
    float* kern   = (float*)(sm + SM_KERN);
    float* chg    = (float*)(sm + SM_CHG);
    float* zmus   = (float*)(sm + SM_ZMU);
    float* pbuf   = (float*)(sm + SM_PBUF);
    float* coords = (float*)(sm + SM_COORD);   // coordsT[j][m], stride 65 words

    const int tid = threadIdx.x;
    const int wid = tid >> 5;
    const int lid = tid & 31;
    const int n0  = blockIdx.x * MB;

    // U quarter 0 async copy up front
    {
        const char* usrc = (const char*)g_Ubf;
        if (tid < UQ_BYTES / 16) cp16(smb + SM_UQ + tid * 16, usrc + (size_t)tid * 16);
        if (tid < UQ_BYTES / 16 - 512)
            cp16(smb + SM_UQ + (tid + 512) * 16, usrc + (size_t)(tid + 512) * 16);
        cp_commit();
    }

    if (tid < MB) {
        int n = n0 + tid;
        gid[tid] = (n < Nc) ? choice[n] : -1;
    }
    chg[tid]  = g_change[tid];
    zmus[tid] = g_zmu[tid];
    if (tid < 136) ((uint2*)(sm + SM_LUT))[tid] = ((const uint2*)g_iup)[tid];
    __syncthreads();

    // ---- phase 1: gather in 4 k-quarters + ZU mma ----
    const int r  = tid >> 3, s8 = tid & 7;
    const int g  = gid[r];
    const float4* zrowg = (const float4*)(Z_all + (size_t)(g < 0 ? 0 : g) * D) + s8 * 4;
    char* zrow = sm + SM_R + r * ZQ_STRIDE + s8 * 32;

    const int zr0 = (wid & 3) * 16;
    const int zch = (wid >> 2) & 1;
    const uint32_t zbase = smb + SM_R + (uint32_t)(zr0 + (lid & 15)) * ZQ_STRIDE +
                           (uint32_t)((lid >> 4) * 16);
    const uint32_t ulane = (uint32_t)((lid & 7) + 8 * ((lid >> 3) & 1)) * U_STRIDE +
                           (uint32_t)(zch * 16 + 8 * (lid >> 4)) * 2;

    float zu[2][4];
    #pragma unroll
    for (int i = 0; i < 2; ++i)
        #pragma unroll
        for (int j = 0; j < 4; ++j) zu[i][j] = 0.f;

    float accn = 0.f;
    for (int q = 0; q < 4; ++q) {
        #pragma unroll
        for (int i = 0; i < 4; ++i) {
            float4 z = make_float4(0.f, 0.f, 0.f, 0.f);
            if (g >= 0) z = zrowg[q * 32 + i];
            int d0 = q * 128 + s8 * 16 + i * 4;
            float a0 = z.x - zmus[d0], a1 = z.y - zmus[d0 + 1];
            float a2 = z.z - zmus[d0 + 2], a3 = z.w - zmus[d0 + 3];
            accn = fmaf(a0, a0, fmaf(a1, a1, fmaf(a2, a2, fmaf(a3, a3, accn))));
            __nv_bfloat162 p0 = __floats2bfloat162_rn(z.x, z.y);
            __nv_bfloat162 p1 = __floats2bfloat162_rn(z.z, z.w);
            *(uint32_t*)(zrow + i * 8)     = *(uint32_t*)&p0;
            *(uint32_t*)(zrow + i * 8 + 4) = *(uint32_t*)&p1;
        }
        if (q == 3) pbuf[tid] = accn;
        if (q < 3) {
            const char* usrc = (const char*)g_Ubf + (size_t)(q + 1) * UQ_BYTES;
            uint32_t ud = smb + SM_UQ + (uint32_t)(((q + 1) & 1) * UQ_BYTES);
            if (tid < UQ_BYTES / 16) cp16(ud + tid * 16, usrc + (size_t)tid * 16);
            if (tid < UQ_BYTES / 16 - 512)
                cp16(ud + (tid + 512) * 16, usrc + (size_t)(tid + 512) * 16);
            cp_commit();
            cp_wait<1>();
        } else {
            cp_wait<0>();
        }
        __syncthreads();
        if (wid < 8) {
            uint32_t ub = smb + SM_UQ + (uint32_t)((q & 1) * UQ_BYTES) + ulane;
            #pragma unroll
            for (int ks = 0; ks < 8; ++ks) {
                uint32_t a[4], b[4];
                ldsm4(a, zbase + (uint32_t)(ks * 32));
                ldsm4t(b, ub + (uint32_t)(ks * 16) * U_STRIDE);
                mma16816(zu[0], a, b);
                mma16816(zu[1], a, b + 2);
            }
        }
        __syncthreads();
    }

    // coordsT[c][m] = ZU - xcU
    if (wid < 8) {
        int r0 = zr0 + (lid >> 2);
        int c0 = (lid & 3) * 2;
        #pragma unroll
        for (int nt = 0; nt < 2; ++nt) {
            int c = zch * 16 + nt * 8 + c0;
            coords[c * CT_STRIDE + r0]           = zu[nt][0] - g_xcU[c];
            coords[(c + 1) * CT_STRIDE + r0]     = zu[nt][1] - g_xcU[c + 1];
            coords[c * CT_STRIDE + r0 + 8]       = zu[nt][2] - g_xcU[c];
            coords[(c + 1) * CT_STRIDE + r0 + 8] = zu[nt][3] - g_xcU[c + 1];
        }
    }
    __syncthreads();

    // ---- secant (threads 0..63) || H build (warps 2..15), all conflict-free ----
    if (tid < MB) {
        float un = 0.f;
        #pragma unroll
        for (int j = 0; j < KK; ++j) {
            float v = coords[j * CT_STRIDE + tid] + g_dU[j];
            un = fmaf(v, v, un);
        }
        float zn = 0.f;
        #pragma unroll
        for (int k = 0; k < 8; ++k) zn += pbuf[tid * 8 + k];
        float C = zn - un;
        float E = __expf(-0.01f * un);
        float x_m2 = C * 0.999f;
        float x_m1 = C;
        bool done = false;
        for (int it = 0; it < 100; ++it) {
            if (done) break;
            float t1 = 1.f - E * __expf(-0.01f * x_m1);
            float f1 = t1 * t1 * x_m1 - C;
            float t2 = 1.f - E * __expf(-0.01f * x_m2);
            float f2 = t2 * t2 * x_m2 - C;
            float fd = f1 - f2;
            if (fabsf(fd) < 1e-6f) fd = (fd >= 0.f) ? 1e-6f : -1e-6f;
            float x = x_m1 - f1 * (x_m1 - x_m2) / fd;
            float step = fabsf(x - x_m1);
            x_m2 = x_m1;
            x_m1 = x;
            done = (step < 1e-6f);
        }
        kern[tid] = __expf(-0.01f * (un + x_m1));
    }
    if (wid >= 2) {
        const unsigned short* lut = (const unsigned short*)(sm + SM_LUT);
        for (int m = wid - 2; m < MB; m += 14) {
            char* hrow = sm + SM_R + m * H_STRIDE;
            #pragma unroll
            for (int it = 0; it < 5; ++it) {
                int gp = lid + it * 32;
                if (gp < 144) {
                    int p = gp * 4;
                    uint32_t w = 0;
                    if (p < PP) {
                        uint2 lu = *(const uint2*)(lut + p);
                        int a0 = lu.x & 255, b0 = (lu.x >> 8) & 255;
                        int a1 = (lu.x >> 16) & 255, b1 = (lu.x >> 24) & 255;
                        int a2 = lu.y & 255, b2 = (lu.y >> 8) & 255;
                        int a3 = (lu.y >> 16) & 255, b3 = (lu.y >> 24) & 255;
                        w = pack4_e4m3(coords[a0 * CT_STRIDE + m] * coords[b0 * CT_STRIDE + m],
                                       coords[a1 * CT_STRIDE + m] * coords[b1 * CT_STRIDE + m],
                                       coords[a2 * CT_STRIDE + m] * coords[b2 * CT_STRIDE + m],
                                       coords[a3 * CT_STRIDE + m] * coords[b3 * CT_STRIDE + m]);
                    }
                    *(uint32_t*)(hrow + p) = w;
                }
            }
        }
    }
    __syncthreads();    // H visible; last barrier

    // ---- main GEMM: 9 chunks, both N-halves, fp16 accumulators ----
    const int mg = (wid >> 3) * 32;
    const uint32_t hlane = smb + SM_R + (uint32_t)(mg + (lid & 15)) * H_STRIDE +
                           (uint32_t)((lid >> 4) * 16);
    const char* vfw = (const char*)g_Vfrag + (uint32_t)((wid & 7) * 2048 + lid * 16);
    const float INV256 = 0.00390625f;

    uint32_t acc16[2][2][4][2];   // [mt][np][nt][reg]
    #pragma unroll
    for (int i = 0; i < 2; ++i)
        #pragma unroll
        for (int j = 0; j < 2; ++j)
            #pragma unroll
            for (int k = 0; k < 4; ++k) {
                acc16[i][j][k][0] = 0u;
                acc16[i][j][k][1] = 0u;
            }

    for (int c = 0; c < NCHUNK; ++c) {
        const uint4* vp0 = (const uint4*)(vfw + (size_t)c * 16384);
        const uint4* vp1 = (const uint4*)(vfw + (size_t)(c + NCHUNK) * 16384);
        const uint32_t koff = (uint32_t)(c * KCH);
        uint32_t a0[4], a1[4];
        // ks = 0
        ldsm4(a0, hlane + koff);
        ldsm4(a1, hlane + (uint32_t)(16 * H_STRIDE) + koff);
        {
            uint4 b0 = vp0[0], b1 = vp0[32];
            mma8h(acc16[0][0][0], a0, b0.x, b0.y);
            mma8h(acc16[0][0][1], a0, b0.z, b0.w);
            mma8h(acc16[0][0][2], a0, b1.x, b1.y);
            mma8h(acc16[0][0][3], a0, b1.z, b1.w);
            mma8h(acc16[1][0][0], a1, b0.x, b0.y);
            mma8h(acc16[1][0][1], a1, b0.z, b0.w);
            mma8h(acc16[1][0][2], a1, b1.x, b1.y);
            mma8h(acc16[1][0][3], a1, b1.z, b1.w);
        }
        {
            uint4 b0 = vp1[0], b1 = vp1[32];
            mma8h(acc16[0][1][0], a0, b0.x, b0.y);
            mma8h(acc16[0][1][1], a0, b0.z, b0.w);
            mma8h(acc16[0][1][2], a0, b1.x, b1.y);
            mma8h(acc16[0][1][3], a0, b1.z, b1.w);
            mma8h(acc16[1][1][0], a1, b0.x, b0.y);
            mma8h(acc16[1][1][1], a1, b0.z, b0.w);
            mma8h(acc16[1][1][2], a1, b1.x, b1.y);
            mma8h(acc16[1][1][3], a1, b1.z, b1.w);
        }
        // ks = 1
        ldsm4(a0, hlane + koff + 32);
        ldsm4(a1, hlane + (uint32_t)(16 * H_STRIDE) + koff + 32);
        {
            uint4 b0 = vp0[64], b1 = vp0[96];
            mma8h(acc16[0][0][0], a0, b0.x, b0.y);
            mma8h(acc16[0][0][1], a0, b0.z, b0.w);
            mma8h(acc16[0][0][2], a0, b1.x, b1.y);
            mma8h(acc16[0][0][3], a0, b1.z, b1.w);
            mma8h(acc16[1][0][0], a1, b0.x, b0.y);
            mma8h(acc16[1][0][1], a1, b0.z, b0.w);
            mma8h(acc16[1][0][2], a1, b1.x, b1.y);
            mma8h(acc16[1][0][3], a1, b1.z, b1.w);
        }
        {
            uint4 b0 = vp1[64], b1 = vp1[96];
            mma8h(acc16[0][1][0], a0, b0.x, b0.y);
            mma8h(acc16[0][1][1], a0, b0.z, b0.w);
            mma8h(acc16[0][1][2], a0, b1.x, b1.y);
            mma8h(acc16[0][1][3], a0, b1.z, b1.w);
            mma8h(acc16[1][1][0], a1, b0.x, b0.y);
            mma8h(acc16[1][1][1], a1, b0.z, b0.w);
            mma8h(acc16[1][1][2], a1, b1.x, b1.y);
            mma8h(acc16[1][1][3], a1, b1.z, b1.w);
        }
    }

    // ---- epilogue: both halves ----
    #pragma unroll
    for (int np = 0; np < 2; ++np) {
        int r0 = mg + (lid >> 2);
        int c0 = np * 256 + (wid & 7) * 32 + (lid & 3) * 2;
        #pragma unroll
        for (int mt = 0; mt < 2; ++mt) {
            int rA = r0 + mt * 16, rB = rA + 8;
            int gA = gid[rA], gB = gid[rB];
            float kA = kern[rA], kB = kern[rB];
            #pragma unroll
            for (int nt = 0; nt < 4; ++nt) {
                int col = c0 + nt * 8;
                float ca = chg[col], cb = chg[col + 1];
                float2 vA = __half22float2(*(__half2*)&acc16[mt][np][nt][0]);
                float2 vB = __half22float2(*(__half2*)&acc16[mt][np][nt][1]);
                if (gA >= 0) {
                    float2 z = *(const float2*)(Z_all + (size_t)gA * D + col);
                    float2 o;
                    o.x = z.x + kA * (ca + vA.x * INV256);
                    o.y = z.y + kA * (cb + vA.y * INV256);
                    *(float2*)(out + (size_t)gA * D + col) = o;
                }
                if (gB >= 0) {
                    float2 z = *(const float2*)(Z_all + (size_t)gB * D + col);
                    float2 o;
                    o.x = z.x + kB * (ca + vB.x * INV256);
                    o.y = z.y + kB * (cb + vB.y * INV256);
                    *(float2*)(out + (size_t)gB * D + col) = o;
                }
            }
        }
    }
}

// ===================== launch =====================
extern "C" void kernel_launch(void* const* d_in, const int* in_sizes, int n_in,
                              void* d_out, int out_size) {
    const float* Z_all  = (const float*)d_in[0];
    const float* U      = (const float*)d_in[1];
    const float* V      = (const float*)d_in[2];
    const float* zmu    = (const float*)d_in[3];
    const float* xc     = (const float*)d_in[4];
    const int*   choice = (const int*)  d_in[5];
    float*       out    = (float*)d_out;
    const int Nc = in_sizes[5];

    if ((size_t)Nc * D != (size_t)in_sizes[0]) {
        cudaMemcpyAsync(d_out, Z_all, (size_t)in_sizes[0] * sizeof(float),
                        cudaMemcpyDeviceToDevice, 0);
    }

    prep_kernel<<<369, 256>>>(U, V, zmu, xc);

    cudaFuncSetAttribute(glayer_fused, cudaFuncAttributeMaxDynamicSharedMemorySize, SM_TOTAL);
    int nblocks = (Nc + MB - 1) / MB;
    glayer_fused<<<nblocks, NTHREADS, SM_TOTAL>>>(Z_all, choice, out, Nc);
}

// round 13
// speedup vs baseline: 1.3780x; 1.0219x over previous
#include <cuda_runtime.h>
#include <cuda_bf16.h>
#include <cuda_fp16.h>
#include <cuda_fp8.h>
#include <math.h>
#include <stdint.h>

#define D        512
#define KK       32
#define PP       528
#define MB       64                // rows per CTA
#define KCH      64
#define NCHUNK   9
#define NTHREADS 512

#define H_STRIDE 592               // 576 + 16; /16 odd
#define ZQ_STRIDE 272
#define U_STRIDE 80
#define UQ_BYTES  (128 * U_STRIDE)
#define CT_STRIDE 65               // coordsT word stride
#define ES_STRIDE 528              // epilogue stage row bytes (264 fp16; 132 words ≡ 4 mod 32)

// ---------- smem ----------
#define SM_GID   0
#define SM_KERN  256
#define SM_CHG   512
#define SM_ZMU   2560
#define SM_LUT   4608              // 1088B
#define SM_PBUF  5696
#define SM_COORD 7744              // 32*65*4 = 8320
#define SM_R     16192             // phase1 ZQ+UQ | phase2 H(37888) | phase3 stage(33792)
#define SM_UQ    33600
#define SM_TOTAL 54080

__device__ float g_change[D];
__device__ float g_zmu[D];
__device__ float g_xcU[KK];
__device__ float g_dU[KK];
__device__ __align__(16) unsigned short g_iup[544];
__device__ __align__(16) unsigned char g_Ubf[512 * U_STRIDE];
// V fragments, K-PERMUTED to match H smem layout
__device__ __align__(16) unsigned char g_Vfrag[18 * 16384];   // 288KB

__device__ __forceinline__ uint32_t smem_u32(const void* p) {
    uint32_t a;
    asm("{ .reg .u64 t; cvta.to.shared.u64 t, %1; cvt.u32.u64 %0, t; }" : "=r"(a) : "l"(p));
    return a;
}
__device__ __forceinline__ void ldsm4(uint32_t* r, uint32_t a) {
    asm volatile("ldmatrix.sync.aligned.m8n8.x4.shared.b16 {%0,%1,%2,%3}, [%4];"
                 : "=r"(r[0]), "=r"(r[1]), "=r"(r[2]), "=r"(r[3]) : "r"(a));
}
__device__ __forceinline__ void ldsm4t(uint32_t* r, uint32_t a) {
    asm volatile("ldmatrix.sync.aligned.m8n8.x4.trans.shared.b16 {%0,%1,%2,%3}, [%4];"
                 : "=r"(r[0]), "=r"(r[1]), "=r"(r[2]), "=r"(r[3]) : "r"(a));
}
__device__ __forceinline__ void mma16816(float* c, const uint32_t* a, const uint32_t* b) {
    asm volatile("mma.sync.aligned.m16n8k16.row.col.f32.bf16.bf16.f32 "
                 "{%0,%1,%2,%3}, {%4,%5,%6,%7}, {%8,%9}, {%0,%1,%2,%3};"
                 : "+f"(c[0]), "+f"(c[1]), "+f"(c[2]), "+f"(c[3])
                 : "r"(a[0]), "r"(a[1]), "r"(a[2]), "r"(a[3]), "r"(b[0]), "r"(b[1]));
}
__device__ __forceinline__ void mma8h(uint32_t* c, const uint32_t* a, uint32_t b0, uint32_t b1) {
    asm volatile("mma.sync.aligned.m16n8k32.row.col.f16.e4m3.e4m3.f16 "
                 "{%0,%1}, {%2,%3,%4,%5}, {%6,%7}, {%0,%1};"
                 : "+r"(c[0]), "+r"(c[1])
                 : "r"(a[0]), "r"(a[1]), "r"(a[2]), "r"(a[3]), "r"(b0), "r"(b1));
}
__device__ __forceinline__ uint32_t pack4_e4m3(float f0, float f1, float f2, float f3) {
    uint32_t r;
    asm("{\n\t.reg .b16 lo, hi;\n\t"
        "cvt.rn.satfinite.e4m3x2.f32 lo, %2, %1;\n\t"
        "cvt.rn.satfinite.e4m3x2.f32 hi, %4, %3;\n\t"
        "mov.b32 %0, {lo, hi};\n\t}"
        : "=r"(r) : "f"(f0), "f"(f1), "f"(f2), "f"(f3));
    return r;
}
__device__ __forceinline__ void cp16(uint32_t saddr, const void* g) {
    asm volatile("cp.async.cg.shared.global [%0], [%1], 16;" :: "r"(saddr), "l"(g));
}
__device__ __forceinline__ void cp_commit() {
    asm volatile("cp.async.commit_group;" ::: "memory");
}
template <int N>
__device__ __forceinline__ void cp_wait() {
    asm volatile("cp.async.wait_group %0;" :: "n"(N) : "memory");
}

// K-permutation: H/V byte position knew  <->  original triu index p
__host__ __device__ __forceinline__ int perm_knew_to_p(int knew) {
    if (knew < 512)
        return 128 * (knew >> 7) + 32 * (knew & 3) + ((knew >> 2) & 31);
    return 512 + 16 * (knew & 3) + ((knew >> 2) & 15);
}

// ===================== prep =====================
__global__ void prep_kernel(const float* __restrict__ U,
                            const float* __restrict__ V,
                            const float* __restrict__ zmu,
                            const float* __restrict__ xc) {
    int b = blockIdx.x, t = threadIdx.x;
    if (b < 288) {
        int idx = b * 256 + t;                 // one fragment u32 word
        int l    = (idx >> 2) & 31;
        int jj   = idx & 3;
        int q    = (idx >> 7) & 1;
        int ks   = (idx >> 8) & 1;
        int ngrp = (idx >> 9) & 7;
        int tt   = idx >> 12;
        int i    = 8 * jj + (l >> 2);
        int nl   = ngrp * 32 + q * 16 + (i & 7) + 8 * ((i >> 4) & 1);
        int koff = ((i >> 3) & 1) * 16 + ks * 32 + (l & 3) * 4;
        int c  = tt % NCHUNK, np = tt / NCHUNK;
        int d  = np * 256 + nl;
        int knew_base = c * KCH + koff;
        float f[4];
        #pragma unroll
        for (int byte = 0; byte < 4; ++byte) {
            int p = perm_knew_to_p(knew_base + byte);
            f[byte] = (p < PP) ? V[(size_t)d * PP + p] * 256.f : 0.f;
        }
        *(uint32_t*)(g_Vfrag + (size_t)idx * 4) = pack4_e4m3(f[0], f[1], f[2], f[3]);
        return;
    }
    if (b < 368) {
        int e = (b - 288) * 256 + t;
        int k = e / 40, n = e - k * 40;
        float v = (n < KK) ? U[k * KK + n] : 0.f;
        *(__nv_bfloat16*)(g_Ubf + k * U_STRIDE + n * 2) = __float2bfloat16(v);
        return;
    }
    __shared__ float pa[256], pb[256], sdiff[KK];
    {
        int j = t & 31, seg = t >> 5;
        float a = 0.f, bb = 0.f;
        for (int i = 0; i < 64; ++i) {
            int d = seg * 64 + i;
            float u = U[d * KK + j];
            a = fmaf(zmu[d], u, a);
            bb = fmaf(xc[d], u, bb);
        }
        pa[t] = a; pb[t] = bb;
    }
    __syncthreads();
    if (t < KK) {
        float sa = 0.f, sb = 0.f;
        for (int s = 0; s < 8; ++s) { sa += pa[s * 32 + t]; sb += pb[s * 32 + t]; }
        g_xcU[t] = sb;
        g_dU[t]  = sb - sa;
        sdiff[t] = sb - sa;
    }
    __syncthreads();
    for (int d = t; d < D; d += 256) {
        float s = 0.f;
        for (int j = 0; j < KK; ++j) s = fmaf(sdiff[j], U[d * KK + j], s);
        g_change[d] = xc[d] - zmu[d] - s;
        g_zmu[d] = zmu[d];
    }
    for (int p = t; p < 544; p += 256) {
        unsigned short v = 0;
        if (p < PP) {
            int i = 0, base = 0;
            while (base + (KK - i) <= p) { base += KK - i; ++i; }
            int j = i + (p - base);
            v = (unsigned short)(i | (j << 8));
        }
        g_iup[p] = v;
    }
}

// ===================== fused main kernel (M=64, occ 2) ==========
__global__ __launch_bounds__(NTHREADS, 2)
void glayer_fused(const float* __restrict__ Z_all,
                  const int*   __restrict__ choice,
                  float*       __restrict__ out,
                  int Nc) {
    extern __shared__ __align__(16) char sm[];
    const uint32_t smb = smem_u32(sm);
    int*   gid    = (int*)(sm + SM_GID);
    float* kern   = (float*)(sm + SM_KERN);
    float* chg    = (float*)(sm + SM_CHG);
    float* zmus   = (float*)(sm + SM_ZMU);
    float* pbuf   = (float*)(sm + SM_PBUF);
    float* coords = (float*)(sm + SM_COORD);   // coordsT[j][m], stride 65 words

    const int tid = threadIdx.x;
    const int wid = tid >> 5;
    const int lid = tid & 31;
    const int n0  = blockIdx.x * MB;

    // U quarter 0 async copy up front
    {
        const char* usrc = (const char*)g_Ubf;
        if (tid < UQ_BYTES / 16) cp16(smb + SM_UQ + tid * 16, usrc + (size_t)tid * 16);
        if (tid < UQ_BYTES / 16 - 512)
            cp16(smb + SM_UQ + (tid + 512) * 16, usrc + (size_t)(tid + 512) * 16);
        cp_commit();
    }

    if (tid < MB) {
        int n = n0 + tid;
        gid[tid] = (n < Nc) ? choice[n] : -1;
    }
    chg[tid]  = g_change[tid];
    zmus[tid] = g_zmu[tid];
    if (tid < 136) ((uint2*)(sm + SM_LUT))[tid] = ((const uint2*)g_iup)[tid];
    __syncthreads();

    // ---- phase 1: gather in 4 k-quarters + ZU mma ----
    const int r  = tid >> 3, s8 = tid & 7;
    const int g  = gid[r];
    const float4* zrowg = (const float4*)(Z_all + (size_t)(g < 0 ? 0 : g) * D) + s8 * 4;
    char* zrow = sm + SM_R + r * ZQ_STRIDE + s8 * 32;

    const int zr0 = (wid & 3) * 16;
    const int zch = (wid >> 2) & 1;
    const uint32_t zbase = smb + SM_R + (uint32_t)(zr0 + (lid & 15)) * ZQ_STRIDE +
                           (uint32_t)((lid >> 4) * 16);
    const uint32_t ulane = (uint32_t)((lid & 7) + 8 * ((lid >> 3) & 1)) * U_STRIDE +
                           (uint32_t)(zch * 16 + 8 * (lid >> 4)) * 2;

    float zu[2][4];
    #pragma unroll
    for (int i = 0; i < 2; ++i)
        #pragma unroll
        for (int j = 0; j < 4; ++j) zu[i][j] = 0.f;

    float accn = 0.f;
    for (int q = 0; q < 4; ++q) {
        #pragma unroll
        for (int i = 0; i < 4; ++i) {
            float4 z = make_float4(0.f, 0.f, 0.f, 0.f);
            if (g >= 0) z = zrowg[q * 32 + i];
            int d0 = q * 128 + s8 * 16 + i * 4;
            float a0 = z.x - zmus[d0], a1 = z.y - zmus[d0 + 1];
            float a2 = z.z - zmus[d0 + 2], a3 = z.w - zmus[d0 + 3];
            accn = fmaf(a0, a0, fmaf(a1, a1, fmaf(a2, a2, fmaf(a3, a3, accn))));
            __nv_bfloat162 p0 = __floats2bfloat162_rn(z.x, z.y);
            __nv_bfloat162 p1 = __floats2bfloat162_rn(z.z, z.w);
            *(uint32_t*)(zrow + i * 8)     = *(uint32_t*)&p0;
            *(uint32_t*)(zrow + i * 8 + 4) = *(uint32_t*)&p1;
        }
        if (q == 3) pbuf[tid] = accn;
        if (q < 3) {
            const char* usrc = (const char*)g_Ubf + (size_t)(q + 1) * UQ_BYTES;
            uint32_t ud = smb + SM_UQ + (uint32_t)(((q + 1) & 1) * UQ_BYTES);
            if (tid < UQ_BYTES / 16) cp16(ud + tid * 16, usrc + (size_t)tid * 16);
            if (tid < UQ_BYTES / 16 - 512)
                cp16(ud + (tid + 512) * 16, usrc + (size_t)(tid + 512) * 16);
            cp_commit();
            cp_wait<1>();
        } else {
            cp_wait<0>();
        }
        __syncthreads();
        if (wid < 8) {
            uint32_t ub = smb + SM_UQ + (uint32_t)((q & 1) * UQ_BYTES) + ulane;
            #pragma unroll
            for (int ks = 0; ks < 8; ++ks) {
                uint32_t a[4], b[4];
                ldsm4(a, zbase + (uint32_t)(ks * 32));
                ldsm4t(b, ub + (uint32_t)(ks * 16) * U_STRIDE);
                mma16816(zu[0], a, b);
                mma16816(zu[1], a, b + 2);
            }
        }
        __syncthreads();
    }

    // coordsT[c][m] = ZU - xcU
    if (wid < 8) {
        int r0 = zr0 + (lid >> 2);
        int c0 = (lid & 3) * 2;
        #pragma unroll
        for (int nt = 0; nt < 2; ++nt) {
            int c = zch * 16 + nt * 8 + c0;
            coords[c * CT_STRIDE + r0]           = zu[nt][0] - g_xcU[c];
            coords[(c + 1) * CT_STRIDE + r0]     = zu[nt][1] - g_xcU[c + 1];
            coords[c * CT_STRIDE + r0 + 8]       = zu[nt][2] - g_xcU[c];
            coords[(c + 1) * CT_STRIDE + r0 + 8] = zu[nt][3] - g_xcU[c + 1];
        }
    }
    __syncthreads();

    // ---- secant (threads 0..63) || permuted H build (warps 2..15) ----
    if (tid < MB) {
        float un = 0.f;
        #pragma unroll
        for (int j = 0; j < KK; ++j) {
            float v = coords[j * CT_STRIDE + tid] + g_dU[j];
            un = fmaf(v, v, un);
        }
        float zn = 0.f;
        #pragma unroll
        for (int k = 0; k < 8; ++k) zn += pbuf[tid * 8 + k];
        float C = zn - un;
        float E = __expf(-0.01f * un);
        float x_m2 = C * 0.999f;
        float x_m1 = C;
        bool done = false;
        for (int it = 0; it < 100; ++it) {
            if (done) break;
            float t1 = 1.f - E * __expf(-0.01f * x_m1);
            float f1 = t1 * t1 * x_m1 - C;
            float t2 = 1.f - E * __expf(-0.01f * x_m2);
            float f2 = t2 * t2 * x_m2 - C;
            float fd = f1 - f2;
            if (fabsf(fd) < 1e-6f) fd = (fd >= 0.f) ? 1e-6f : -1e-6f;
            float x = x_m1 - f1 * (x_m1 - x_m2) / fd;
            float step = fabsf(x - x_m1);
            x_m2 = x_m1;
            x_m1 = x;
            done = (step < 1e-6f);
        }
        kern[tid] = __expf(-0.01f * (un + x_m1));
    }
    if (wid >= 2) {
        const unsigned short* lut = (const unsigned short*)(sm + SM_LUT);
        for (int m = wid - 2; m < MB; m += 14) {
            char* hrow = sm + SM_R + m * H_STRIDE;
            #pragma unroll
            for (int it = 0; it < 5; ++it) {
                if (it == 4 && lid >= 16) break;
                float f[4];
                #pragma unroll
                for (int j = 0; j < 4; ++j) {
                    int p = (it < 4) ? (128 * it + 32 * j + lid)
                                     : (512 + 16 * j + lid);
                    float h = 0.f;
                    if (p < PP) {
                        unsigned pr = lut[p];
                        h = coords[(pr & 31) * CT_STRIDE + m] *
                            coords[((pr >> 8) & 31) * CT_STRIDE + m];
                    }
                    f[j] = h;
                }
                *(uint32_t*)(hrow + it * 128 + lid * 4) =
                    pack4_e4m3(f[0], f[1], f[2], f[3]);
            }
        }
    }
    __syncthreads();

    // ---- main GEMM: 9 chunks, both N-halves, fp16 accumulators ----
    const int mg = (wid >> 3) * 32;
    const uint32_t hlane = smb + SM_R + (uint32_t)(mg + (lid & 15)) * H_STRIDE +
                           (uint32_t)((lid >> 4) * 16);
    const char* vfw = (const char*)g_Vfrag + (uint32_t)((wid & 7) * 2048 + lid * 16);
    const float INV256 = 0.00390625f;

    uint32_t acc16[2][2][4][2];   // [mt][np][nt][reg]
    #pragma unroll
    for (int i = 0; i < 2; ++i)
        #pragma unroll
        for (int j = 0; j < 2; ++j)
            #pragma unroll
            for (int k = 0; k < 4; ++k) {
                acc16[i][j][k][0] = 0u;
                acc16[i][j][k][1] = 0u;
            }

    for (int c = 0; c < NCHUNK; ++c) {
        const uint4* vp0 = (const uint4*)(vfw + (size_t)c * 16384);
        const uint4* vp1 = (const uint4*)(vfw + (size_t)(c + NCHUNK) * 16384);
        const uint32_t koff = (uint32_t)(c * KCH);
        uint32_t a0[4], a1[4];
        ldsm4(a0, hlane + koff);
        ldsm4(a1, hlane + (uint32_t)(16 * H_STRIDE) + koff);
        {
            uint4 b0 = vp0[0], b1 = vp0[32];
            mma8h(acc16[0][0][0], a0, b0.x, b0.y);
            mma8h(acc16[0][0][1], a0, b0.z, b0.w);
            mma8h(acc16[0][0][2], a0, b1.x, b1.y);
            mma8h(acc16[0][0][3], a0, b1.z, b1.w);
            mma8h(acc16[1][0][0], a1, b0.x, b0.y);
            mma8h(acc16[1][0][1], a1, b0.z, b0.w);
            mma8h(acc16[1][0][2], a1, b1.x, b1.y);
            mma8h(acc16[1][0][3], a1, b1.z, b1.w);
        }
        {
            uint4 b0 = vp1[0], b1 = vp1[32];
            mma8h(acc16[0][1][0], a0, b0.x, b0.y);
            mma8h(acc16[0][1][1], a0, b0.z, b0.w);
            mma8h(acc16[0][1][2], a0, b1.x, b1.y);
            mma8h(acc16[0][1][3], a0, b1.z, b1.w);
            mma8h(acc16[1][1][0], a1, b0.x, b0.y);
            mma8h(acc16[1][1][1], a1, b0.z, b0.w);
            mma8h(acc16[1][1][2], a1, b1.x, b1.y);
            mma8h(acc16[1][1][3], a1, b1.z, b1.w);
        }
        ldsm4(a0, hlane + koff + 32);
        ldsm4(a1, hlane + (uint32_t)(16 * H_STRIDE) + koff + 32);
        {
            uint4 b0 = vp0[64], b1 = vp0[96];
            mma8h(acc16[0][0][0], a0, b0.x, b0.y);
            mma8h(acc16[0][0][1], a0, b0.z, b0.w);
            mma8h(acc16[0][0][2], a0, b1.x, b1.y);
            mma8h(acc16[0][0][3], a0, b1.z, b1.w);
            mma8h(acc16[1][0][0], a1, b0.x, b0.y);
            mma8h(acc16[1][0][1], a1, b0.z, b0.w);
            mma8h(acc16[1][0][2], a1, b1.x, b1.y);
            mma8h(acc16[1][0][3], a1, b1.z, b1.w);
        }
        {
            uint4 b0 = vp1[64], b1 = vp1[96];
            mma8h(acc16[0][1][0], a0, b0.x, b0.y);
            mma8h(acc16[0][1][1], a0, b0.z, b0.w);
            mma8h(acc16[0][1][2], a0, b1.x, b1.y);
            mma8h(acc16[0][1][3], a0, b1.z, b1.w);
            mma8h(acc16[1][1][0], a1, b0.x, b0.y);
            mma8h(acc16[1][1][1], a1, b0.z, b0.w);
            mma8h(acc16[1][1][2], a1, b1.x, b1.y);
            mma8h(acc16[1][1][3], a1, b1.z, b1.w);
        }
    }
    __syncthreads();    // H region dead; reuse for epilogue staging

    // ---- epilogue: stage fp16 accs to smem, then fully coalesced gmem ----
    #pragma unroll
    for (int np = 0; np < 2; ++np) {
        {   // stage: conflict-free STS.32
            int r0 = mg + (lid >> 2);
            int cb = (wid & 7) * 32 + (lid & 3) * 2;
            #pragma unroll
            for (int mt = 0; mt < 2; ++mt)
                #pragma unroll
                for (int nt = 0; nt < 4; ++nt) {
                    int col = cb + nt * 8;
                    *(uint32_t*)(sm + SM_R + (r0 + mt * 16) * ES_STRIDE + col * 2) =
                        acc16[mt][np][nt][0];
                    *(uint32_t*)(sm + SM_R + (r0 + mt * 16 + 8) * ES_STRIDE + col * 2) =
                        acc16[mt][np][nt][1];
                }
        }
        __syncthreads();
        {   // read + dense float4 gmem
            int rr = tid >> 3, q8 = tid & 7;
            int gg = gid[rr];
            float kr = kern[rr];
            if (gg >= 0) {
                const float4* zr4 = (const float4*)(Z_all + (size_t)gg * D + np * 256);
                float4* or4 = (float4*)(out + (size_t)gg * D + np * 256);
                #pragma unroll
                for (int i = 0; i < 4; ++i) {
                    uint4 w = *(const uint4*)(sm + SM_R + rr * ES_STRIDE + i * 128 + q8 * 16);
                    float2 f0 = __half22float2(*(__half2*)&w.x);
                    float2 f1 = __half22float2(*(__half2*)&w.y);
                    float2 f2 = __half22float2(*(__half2*)&w.z);
                    float2 f3 = __half22float2(*(__half2*)&w.w);
                    int cg = np * 256 + i * 64 + q8 * 8;
                    int ci = i * 16 + q8 * 2;
                    float4 z0 = zr4[ci], z1 = zr4[ci + 1];
                    float4 o0, o1;
                    o0.x = z0.x + kr * (chg[cg]     + f0.x * INV256);
                    o0.y = z0.y + kr * (chg[cg + 1] + f0.y * INV256);
                    o0.z = z0.z + kr * (chg[cg + 2] + f1.x * INV256);
                    o0.w = z0.w + kr * (chg[cg + 3] + f1.y * INV256);
                    o1.x = z1.x + kr * (chg[cg + 4] + f2.x * INV256);
                    o1.y = z1.y + kr * (chg[cg + 5] + f2.y * INV256);
                    o1.z = z1.z + kr * (chg[cg + 6] + f3.x * INV256);
                    o1.w = z1.w + kr * (chg[cg + 7] + f3.y * INV256);
                    or4[ci]     = o0;
                    or4[ci + 1] = o1;
                }
            }
        }
        if (np == 0) __syncthreads();
    }
}

// ===================== launch =====================
extern "C" void kernel_launch(void* const* d_in, const int* in_sizes, int n_in,
                              void* d_out, int out_size) {
    const float* Z_all  = (const float*)d_in[0];
    const float* U      = (const float*)d_in[1];
    const float* V      = (const float*)d_in[2];
    const float* zmu    = (const float*)d_in[3];
    const float* xc     = (const float*)d_in[4];
    const int*   choice = (const int*)  d_in[5];
    float*       out    = (float*)d_out;
    const int Nc = in_sizes[5];

    if ((size_t)Nc * D != (size_t)in_sizes[0]) {
        cudaMemcpyAsync(d_out, Z_all, (size_t)in_sizes[0] * sizeof(float),
                        cudaMemcpyDeviceToDevice, 0);
    }

    prep_kernel<<<369, 256>>>(U, V, zmu, xc);

    cudaFuncSetAttribute(glayer_fused, cudaFuncAttributeMaxDynamicSharedMemorySize, SM_TOTAL);
    int nblocks = (Nc + MB - 1) / MB;
    glayer_fused<<<nblocks, NTHREADS, SM_TOTAL>>>(Z_all, choice, out, Nc);
}